// round 5
// baseline (speedup 1.0000x reference)
#include <cuda_runtime.h>
#include <cstdint>

#define Bb 64
#define Nn 128
// DIN = DOUT = 64

__device__ __forceinline__ unsigned tf32r(float x) {
    unsigned u;
    asm("cvt.rna.tf32.f32 %0, %1;" : "=r"(u) : "f"(x));
    return u;
}

// D += A(16x8,row) * B(8x8,col), tf32 inputs as b32 regs, f32 accum.
// Empirically validated register->element map (round-3/4 error algebra):
//   a0=(g,ks0) a1=(g+8,ks0) a2=(g,ks1) a3=(g+8,ks1); b0=(ks0,g) b1=(ks1,g)
//   with ks0=tg, ks1=tg+4 used consistently for A and B (k-maps self-correct).
//   c0=(g,2tg) c1=(g,2tg+1) c2=(g+8,2tg) c3=(g+8,2tg+1)
#define MMA_TF32(d, a0, a1, a2, a3, b0, b1) \
    asm volatile("mma.sync.aligned.m16n8k8.row.col.f32.tf32.tf32.f32 " \
        "{%0,%1,%2,%3}, {%4,%5,%6,%7}, {%8,%9}, {%0,%1,%2,%3};" \
        : "+f"((d)[0]), "+f"((d)[1]), "+f"((d)[2]), "+f"((d)[3]) \
        : "r"(__float_as_uint(a0)), "r"(__float_as_uint(a1)), \
          "r"(__float_as_uint(a2)), "r"(__float_as_uint(a3)), \
          "r"(__float_as_uint(b0)), "r"(__float_as_uint(b1)))

// ---------------------------------------------------------------------------
// Device scratch
// ---------------------------------------------------------------------------
__device__ unsigned char g_idx[Bb * Nn * Nn];   // per-(b,j) nz(k) lists (128B rows)
__device__ int           g_cnt[Bb * Nn];
__device__ float2        g_wp[64 * 64];         // (hi, lo) tf32 split of W[d][e]

// ---------------------------------------------------------------------------
__global__ void build_cols_kernel(const float* __restrict__ A) {
    int b = blockIdx.x;
    int j = threadIdx.x;
    const float* Ab = A + (size_t)b * Nn * Nn;
    unsigned char* lst = g_idx + ((size_t)(b * Nn + j)) * Nn;
    int cnt = 0;
    #pragma unroll 4
    for (int k = 0; k < Nn; ++k) {
        if (Ab[k * Nn + j] != 0.0f) lst[cnt++] = (unsigned char)k;
    }
    g_cnt[b * Nn + j] = cnt;
}

__global__ void prep_w_kernel(const float* __restrict__ W) {
    int f = blockIdx.x * 256 + threadIdx.x;     // 0..4095
    if (f < 4096) {
        float w = W[f];
        float hi = __uint_as_float(tf32r(w));
        float lo = __uint_as_float(tf32r(w - hi));
        g_wp[f] = make_float2(hi, lo);
    }
}

// ---------------------------------------------------------------------------
// Main kernel: one CTA per (b,i), 256 threads (8 warps).
//   G1 (warps 0-3): tX[k][e] = X[b,i,k,:]·W[:,e]  via mma.sync tf32 3-pass
//   G2 (all warps): out[b,i,j][e] = sum_{k in nz(b,j)} tX[k][e] + cnt_j*bias[e]
//
// smem (floats):
//   [0, 16896)      sXT: f32x2 (hi,lo) of X^T; f32x2 index d*132 + k
//                   (after G1, overlaid by tX: row k at 68*k, 64 floats, 4 pad)
//   [16896, 25600)  sWp: f32x2 (hi,lo) of W;   f32x2 index d*68 + e
//   [25600, 25664)  bias
// ---------------------------------------------------------------------------
static constexpr int SMEM_FLOATS = 25664;
static constexpr int SMEM_BYTES  = SMEM_FLOATS * 4;   // 102,656

__global__ __launch_bounds__(256, 2)
void ngnn_mma_kernel(const float* __restrict__ X,
                     const float* __restrict__ bias,
                     float* __restrict__ out) {
    extern __shared__ float sm[];
    float2* sXT   = (float2*)sm;            // [d*132 + k]
    float*  tX    = sm;                     // row k at 68*k (no overlap: 68 >= 64+4)
    float2* sWp   = (float2*)(sm + 16896);  // [d*68 + e]
    float*  sbias = sm + 25600;

    const int i = blockIdx.x;
    const int b = blockIdx.y;
    const int t = threadIdx.x;
    const int warp = t >> 5;
    const int lane = t & 31;

    // ---- prologue: X -> sXT (transposed, tf32 hi/lo pairs), W -> sWp ----
    {
        const int k = t & 127, h = t >> 7;
        const float4* xr = (const float4*)(X + (((size_t)b * Nn + i) * Nn + k) * 64 + h * 32);
        #pragma unroll
        for (int m = 0; m < 8; ++m) {
            float4 v = xr[m];
            float vv[4] = {v.x, v.y, v.z, v.w};
            #pragma unroll
            for (int q = 0; q < 4; ++q) {
                int d = h * 32 + m * 4 + q;
                float hi = __uint_as_float(tf32r(vv[q]));
                float lo = __uint_as_float(tf32r(vv[q] - hi));
                sXT[d * 132 + k] = make_float2(hi, lo);
            }
        }
        #pragma unroll
        for (int r = 0; r < 16; ++r) {
            int f = r * 256 + t;                 // coalesced
            int d = f >> 6, e = f & 63;
            sWp[d * 68 + e] = g_wp[f];
        }
        if (t < 64) sbias[t] = bias[t];
    }
    __syncthreads();

    // ---- G1: warps 0-3, each owns 2 M-tiles (rows 32w..32w+31) ----
    float acc[2][8][4];
    if (warp < 4) {
        #pragma unroll
        for (int mt = 0; mt < 2; ++mt)
            #pragma unroll
            for (int nt = 0; nt < 8; ++nt)
                #pragma unroll
                for (int c = 0; c < 4; ++c) acc[mt][nt][c] = 0.0f;

        const int g  = lane >> 2;
        const int tg = lane & 3;
        #pragma unroll
        for (int s = 0; s < 8; ++s) {
            const int d0 = tg + 8 * s;           // k-slot ks0
            const int d1 = d0 + 4;               // k-slot ks1
            float2 A0[2], A1[2], A2[2], A3[2];
            #pragma unroll
            for (int mt = 0; mt < 2; ++mt) {
                const int kb = warp * 32 + mt * 16 + g;
                A0[mt] = sXT[d0 * 132 + kb];        // (row g,   ks0)
                A1[mt] = sXT[d0 * 132 + kb + 8];    // (row g+8, ks0)
                A2[mt] = sXT[d1 * 132 + kb];        // (row g,   ks1)
                A3[mt] = sXT[d1 * 132 + kb + 8];    // (row g+8, ks1)
            }
            #pragma unroll
            for (int nt = 0; nt < 8; ++nt) {
                const int e = g + 8 * nt;
                const float2 B0 = sWp[d0 * 68 + e]; // (ks0, col g)
                const float2 B1 = sWp[d1 * 68 + e]; // (ks1, col g)
                #pragma unroll
                for (int mt = 0; mt < 2; ++mt) {
                    MMA_TF32(acc[mt][nt], A0[mt].x, A1[mt].x, A2[mt].x, A3[mt].x, B0.x, B1.x); // hi*Whi
                    MMA_TF32(acc[mt][nt], A0[mt].y, A1[mt].y, A2[mt].y, A3[mt].y, B0.x, B1.x); // lo*Whi
                    MMA_TF32(acc[mt][nt], A0[mt].x, A1[mt].x, A2[mt].x, A3[mt].x, B0.y, B1.y); // hi*Wlo
                }
            }
        }
    }
    __syncthreads();   // all sXT reads done before tX overlay writes

    // ---- epilogue: acc -> tX rows (stride 68, no overlap) ----
    if (warp < 4) {
        const int g  = lane >> 2;
        const int tg = lane & 3;
        #pragma unroll
        for (int mt = 0; mt < 2; ++mt) {
            const int k0 = warp * 32 + mt * 16 + g;   // acc c0,c1 row
            const int k1 = k0 + 8;                    // acc c2,c3 row
            float* r0 = tX + 68 * k0;
            float* r1 = tX + 68 * k1;
            #pragma unroll
            for (int nt = 0; nt < 8; ++nt) {
                const int e = 8 * nt + 2 * tg;        // cols 2tg, 2tg+1
                *(float2*)(r0 + e) = make_float2(acc[mt][nt][0], acc[mt][nt][1]);
                *(float2*)(r1 + e) = make_float2(acc[mt][nt][2], acc[mt][nt][3]);
            }
        }
    }
    __syncthreads();

    // ---- G2: warp per j (16 each); lane owns e-pair {2*lane, 2*lane+1} ----
    // Row reads are warp-uniform in k -> consecutive float2s -> conflict-free.
    {
        const float2 bp = ((const float2*)sbias)[lane];
        const unsigned char* bl = g_idx + (size_t)b * Nn * Nn;
        float* outp = out + (((size_t)b * Nn + i) * Nn) * 64;
        #pragma unroll 2
        for (int jj = 0; jj < 16; ++jj) {
            const int j = warp * 16 + jj;
            const int cnt = __ldg(&g_cnt[b * Nn + j]);
            const unsigned* lst = (const unsigned*)(bl + (size_t)j * Nn);
            float ax = bp.x * (float)cnt;
            float ay = bp.y * (float)cnt;
            for (int c = 0; c < cnt; c += 4) {
                const unsigned u = __ldg(&lst[c >> 2]);
                const int rem = cnt - c;
                #pragma unroll
                for (int q = 0; q < 4; ++q) {
                    if (q < rem) {
                        const int k = (u >> (8 * q)) & 255;
                        const float2 v = *(const float2*)(tX + 68 * k + 2 * lane);
                        ax += v.x;
                        ay += v.y;
                    }
                }
            }
            *(float2*)(outp + (size_t)j * 64 + 2 * lane) = make_float2(ax, ay);
        }
    }
}

// ---------------------------------------------------------------------------
extern "C" void kernel_launch(void* const* d_in, const int* in_sizes, int n_in,
                              void* d_out, int out_size) {
    const float* X    = (const float*)d_in[0];  // [B,N,N,DIN]
    const float* A    = (const float*)d_in[1];  // [B,N,N]
    const float* W    = (const float*)d_in[2];  // [DIN,DOUT]
    const float* bias = (const float*)d_in[3];  // [DOUT]
    float* out = (float*)d_out;                 // [B,N,N,DOUT]

    build_cols_kernel<<<Bb, Nn>>>(A);
    prep_w_kernel<<<16, 256>>>(W);

    cudaFuncSetAttribute(ngnn_mma_kernel,
                         cudaFuncAttributeMaxDynamicSharedMemorySize, SMEM_BYTES);
    dim3 grid(Nn, Bb);
    ngnn_mma_kernel<<<grid, 256, SMEM_BYTES>>>(X, bias, out);
}

// round 6
// speedup vs baseline: 1.3587x; 1.3587x over previous
#include <cuda_runtime.h>
#include <cstdint>

#define Bb 64
#define Nn 128
// DIN = DOUT = 64

__device__ __forceinline__ unsigned tf32r(float x) {
    unsigned u;
    asm("cvt.rna.tf32.f32 %0, %1;" : "=r"(u) : "f"(x));
    return u;
}

// D += A(16x8,row) * B(8x8,col), tf32 as b32 regs, f32 accum.
// Validated map (round-5 PASS): a0=(g,ks0) a1=(g+8,ks0) a2=(g,ks1) a3=(g+8,ks1)
// b0=(ks0,g) b1=(ks1,g), ks0=tg, ks1=tg+4; c0/c1=(g,2tg/2tg+1) c2/c3=(g+8,...)
#define MMA_TF32(d, a0, a1, a2, a3, b0, b1) \
    asm volatile("mma.sync.aligned.m16n8k8.row.col.f32.tf32.tf32.f32 " \
        "{%0,%1,%2,%3}, {%4,%5,%6,%7}, {%8,%9}, {%0,%1,%2,%3};" \
        : "+f"((d)[0]), "+f"((d)[1]), "+f"((d)[2]), "+f"((d)[3]) \
        : "r"(__float_as_uint(a0)), "r"(__float_as_uint(a1)), \
          "r"(__float_as_uint(a2)), "r"(__float_as_uint(a3)), \
          "r"(__float_as_uint(b0)), "r"(__float_as_uint(b1)))

// ---------------------------------------------------------------------------
__device__ unsigned char g_idx[Bb * Nn * Nn];   // per-(b,j) nz(k) lists
__device__ int           g_cnt[Bb * Nn];
__device__ float2        g_wp[64 * 64];         // (hi,lo) tf32 split of W[d][e]

// ---------------------------------------------------------------------------
// Prep: warp-ballot column compaction of A + W split (folded in).
// 64 blocks x 256 threads; warp w handles columns j = 16w..16w+15.
// ---------------------------------------------------------------------------
__global__ void build_kernel(const float* __restrict__ A,
                             const float* __restrict__ W) {
    const int b = blockIdx.x;
    const int t = threadIdx.x;
    const int w = t >> 5, lane = t & 31;

    if (t < 64) {                                // W split: block b does 64 elems
        int f = b * 64 + t;
        float wv = W[f];
        float hi = __uint_as_float(tf32r(wv));
        float lo = __uint_as_float(tf32r(wv - hi));
        g_wp[f] = make_float2(hi, lo);
    }

    const float* Ab = A + (size_t)b * Nn * Nn;
    #pragma unroll 1
    for (int jj = 0; jj < 16; ++jj) {
        const int j = w * 16 + jj;
        unsigned m[4];
        #pragma unroll
        for (int q = 0; q < 4; ++q) {
            float v = Ab[(size_t)(lane + 32 * q) * Nn + j];
            m[q] = __ballot_sync(0xFFFFFFFFu, v != 0.0f);
        }
        int pre[4];
        pre[0] = 0;
        pre[1] = __popc(m[0]);
        pre[2] = pre[1] + __popc(m[1]);
        pre[3] = pre[2] + __popc(m[2]);
        const int total = pre[3] + __popc(m[3]);
        unsigned char* lst = g_idx + ((size_t)(b * Nn + j)) * Nn;
        const unsigned below = (1u << lane) - 1u;
        #pragma unroll
        for (int q = 0; q < 4; ++q) {
            if ((m[q] >> lane) & 1u) {
                int pos = pre[q] + __popc(m[q] & below);
                lst[pos] = (unsigned char)(lane + 32 * q);
            }
        }
        if (lane == 0) g_cnt[b * Nn + j] = total;
    }
}

// ---------------------------------------------------------------------------
// Main: one CTA per (b,i), 256 threads (8 warps), 3 CTAs/SM.
//   G1 (ALL warps): warp w computes tX rows [16w,16w+16) via tf32 3-pass MMA.
//   G2: warp per 16 j: out[b,i,j] = sum_{k in nz} tX[k] + cnt_j*bias.
// smem (floats, 17472 = 69,888 B):
//   [0, 8704)      sX: fp32 X^T, [d*136 + k]  (conflict-free: 8tg+g banks)
//                  overlaid after G1 by tX: row k at 68k (64 used + 4 pad)
//   [8704, 17408)  sW2: f32x2 (hi,lo) of W, [d*68 + e] (8tg+2g banks)
//   [17408, 17472) bias
// ---------------------------------------------------------------------------
static constexpr int SMEM_FLOATS = 17472;
static constexpr int SMEM_BYTES  = SMEM_FLOATS * 4;   // 69,888

__global__ __launch_bounds__(256, 3)
void ngnn_mma_kernel(const float* __restrict__ X,
                     const float* __restrict__ bias,
                     float* __restrict__ out) {
    extern __shared__ float sm[];
    float*  sX    = sm;                     // [d*136 + k]
    float*  tX    = sm;                     // row k at 68*k (overlay)
    float2* sW2   = (float2*)(sm + 8704);   // [d*68 + e]
    float*  sbias = sm + 17408;

    const int i = blockIdx.x;
    const int b = blockIdx.y;
    const int t = threadIdx.x;
    const int warp = t >> 5;
    const int lane = t & 31;

    // ---- prologue ----
    {
        const int k = t & 127, h = t >> 7;
        const float4* xr = (const float4*)(X + (((size_t)b * Nn + i) * Nn + k) * 64 + h * 32);
        #pragma unroll
        for (int m = 0; m < 8; ++m) {
            float4 v = xr[m];
            const int d = h * 32 + m * 4;
            sX[(d + 0) * 136 + k] = v.x;
            sX[(d + 1) * 136 + k] = v.y;
            sX[(d + 2) * 136 + k] = v.z;
            sX[(d + 3) * 136 + k] = v.w;
        }
        #pragma unroll
        for (int r = 0; r < 16; ++r) {
            int f = r * 256 + t;                 // coalesced LDG.64
            int d = f >> 6, e = f & 63;
            sW2[d * 68 + e] = g_wp[f];
        }
        if (t < 64) sbias[t] = bias[t];
    }
    __syncthreads();

    // ---- G1: every warp owns one 16-row M-tile ----
    float acc[8][4];
    #pragma unroll
    for (int nt = 0; nt < 8; ++nt)
        #pragma unroll
        for (int c = 0; c < 4; ++c) acc[nt][c] = 0.0f;

    {
        const int g  = lane >> 2;
        const int tg = lane & 3;
        const int kb = warp * 16 + g;
        #pragma unroll
        for (int s = 0; s < 8; ++s) {
            const int d0 = tg + 8 * s;       // ks0
            const int d1 = d0 + 4;           // ks1
            const float x00 = sX[d0 * 136 + kb];
            const float x10 = sX[d0 * 136 + kb + 8];
            const float x01 = sX[d1 * 136 + kb];
            const float x11 = sX[d1 * 136 + kb + 8];
            const float h00 = __uint_as_float(tf32r(x00));
            const float h10 = __uint_as_float(tf32r(x10));
            const float h01 = __uint_as_float(tf32r(x01));
            const float h11 = __uint_as_float(tf32r(x11));
            const float l00 = __uint_as_float(tf32r(x00 - h00));
            const float l10 = __uint_as_float(tf32r(x10 - h10));
            const float l01 = __uint_as_float(tf32r(x01 - h01));
            const float l11 = __uint_as_float(tf32r(x11 - h11));
            #pragma unroll
            for (int nt = 0; nt < 8; ++nt) {
                const int e = 8 * nt + g;
                const float2 B0 = sW2[d0 * 68 + e];  // (ks0, col g) hi,lo
                const float2 B1 = sW2[d1 * 68 + e];  // (ks1, col g) hi,lo
                MMA_TF32(acc[nt], h00, h10, h01, h11, B0.x, B1.x); // hi*Whi
                MMA_TF32(acc[nt], l00, l10, l01, l11, B0.x, B1.x); // lo*Whi
                MMA_TF32(acc[nt], h00, h10, h01, h11, B0.y, B1.y); // hi*Wlo
            }
        }
    }
    __syncthreads();   // all sX reads complete before tX overlay

    // ---- epilogue: acc -> tX rows (stride 68) ----
    {
        const int g  = lane >> 2;
        const int tg = lane & 3;
        const int k0 = warp * 16 + g;
        float* r0 = tX + 68 * k0;
        float* r1 = tX + 68 * (k0 + 8);
        #pragma unroll
        for (int nt = 0; nt < 8; ++nt) {
            const int e = 8 * nt + 2 * tg;
            *(float2*)(r0 + e) = make_float2(acc[nt][0], acc[nt][1]);
            *(float2*)(r1 + e) = make_float2(acc[nt][2], acc[nt][3]);
        }
    }
    __syncthreads();

    // ---- G2: warp per j (16 each); lane owns e-pair {2*lane, 2*lane+1} ----
    {
        const float2 bp = ((const float2*)sbias)[lane];
        const unsigned char* bl = g_idx + (size_t)b * Nn * Nn;
        float* outp = out + (((size_t)b * Nn + i) * Nn) * 64;
        #pragma unroll 2
        for (int jj = 0; jj < 16; ++jj) {
            const int j = warp * 16 + jj;
            const int cnt = __ldg(&g_cnt[b * Nn + j]);
            const unsigned* lst = (const unsigned*)(bl + (size_t)j * Nn);
            float ax = bp.x * (float)cnt;
            float ay = bp.y * (float)cnt;
            for (int c = 0; c < cnt; c += 4) {
                const unsigned u = __ldg(&lst[c >> 2]);
                const int rem = cnt - c;
                #pragma unroll
                for (int q = 0; q < 4; ++q) {
                    if (q < rem) {
                        const int k = (u >> (8 * q)) & 255;
                        const float2 v = *(const float2*)(tX + 68 * k + 2 * lane);
                        ax += v.x;
                        ay += v.y;
                    }
                }
            }
            *(float2*)(outp + (size_t)j * 64 + 2 * lane) = make_float2(ax, ay);
        }
    }
}

// ---------------------------------------------------------------------------
extern "C" void kernel_launch(void* const* d_in, const int* in_sizes, int n_in,
                              void* d_out, int out_size) {
    const float* X    = (const float*)d_in[0];  // [B,N,N,DIN]
    const float* A    = (const float*)d_in[1];  // [B,N,N]
    const float* W    = (const float*)d_in[2];  // [DIN,DOUT]
    const float* bias = (const float*)d_in[3];  // [DOUT]
    float* out = (float*)d_out;                 // [B,N,N,DOUT]

    build_kernel<<<Bb, 256>>>(A, W);

    cudaFuncSetAttribute(ngnn_mma_kernel,
                         cudaFuncAttributeMaxDynamicSharedMemorySize, SMEM_BYTES);
    dim3 grid(Nn, Bb);
    ngnn_mma_kernel<<<grid, 256, SMEM_BYTES>>>(X, bias, out);
}

// round 7
// speedup vs baseline: 1.3628x; 1.0030x over previous
#include <cuda_runtime.h>
#include <cstdint>

#define Bb 64
#define Nn 128
// DIN = DOUT = 64

__device__ __forceinline__ unsigned tf32r(float x) {
    unsigned u;
    asm("cvt.rna.tf32.f32 %0, %1;" : "=r"(u) : "f"(x));
    return u;
}

// Validated (round-5/6 PASS): a0=(g,ks0) a1=(g+8,ks0) a2=(g,ks1) a3=(g+8,ks1)
// b0=(ks0,g) b1=(ks1,g); c0/c1=(g,2tg/2tg+1), c2/c3=(g+8,...)
#define MMA_TF32(d, a0, a1, a2, a3, b0, b1) \
    asm volatile("mma.sync.aligned.m16n8k8.row.col.f32.tf32.tf32.f32 " \
        "{%0,%1,%2,%3}, {%4,%5,%6,%7}, {%8,%9}, {%0,%1,%2,%3};" \
        : "+f"((d)[0]), "+f"((d)[1]), "+f"((d)[2]), "+f"((d)[3]) \
        : "r"(__float_as_uint(a0)), "r"(__float_as_uint(a1)), \
          "r"(__float_as_uint(a2)), "r"(__float_as_uint(a3)), \
          "r"(__float_as_uint(b0)), "r"(__float_as_uint(b1)))

#define ADD_F32X2(out, a, b) asm("add.rn.f32x2 %0, %1, %2;" : "=l"(out) : "l"(a), "l"(b))

// ---------------------------------------------------------------------------
__device__ unsigned short g_off[Bb * Nn * Nn];  // per-(b,j) nz byte-offsets k*272
__device__ int            g_cnt[Bb * Nn];
__device__ float2         g_wp[64 * 64];        // (hi,lo) tf32 split of W[d][e]

// ---------------------------------------------------------------------------
// Prep: warp-ballot column compaction of A (emitting k*272 byte offsets) + W split.
// ---------------------------------------------------------------------------
__global__ void build_kernel(const float* __restrict__ A,
                             const float* __restrict__ W) {
    const int b = blockIdx.x;
    const int t = threadIdx.x;
    const int w = t >> 5, lane = t & 31;

    if (t < 64) {
        int f = b * 64 + t;
        float wv = W[f];
        float hi = __uint_as_float(tf32r(wv));
        float lo = __uint_as_float(tf32r(wv - hi));
        g_wp[f] = make_float2(hi, lo);
    }

    const float* Ab = A + (size_t)b * Nn * Nn;
    #pragma unroll 1
    for (int jj = 0; jj < 16; ++jj) {
        const int j = w * 16 + jj;
        unsigned m[4];
        #pragma unroll
        for (int q = 0; q < 4; ++q) {
            float v = Ab[(size_t)(lane + 32 * q) * Nn + j];
            m[q] = __ballot_sync(0xFFFFFFFFu, v != 0.0f);
        }
        int pre[4];
        pre[0] = 0;
        pre[1] = __popc(m[0]);
        pre[2] = pre[1] + __popc(m[1]);
        pre[3] = pre[2] + __popc(m[2]);
        const int total = pre[3] + __popc(m[3]);
        unsigned short* lst = g_off + ((size_t)(b * Nn + j)) * Nn;
        const unsigned below = (1u << lane) - 1u;
        #pragma unroll
        for (int q = 0; q < 4; ++q) {
            if ((m[q] >> lane) & 1u) {
                int pos = pre[q] + __popc(m[q] & below);
                lst[pos] = (unsigned short)((lane + 32 * q) * 272);
            }
        }
        if (lane == 0) g_cnt[b * Nn + j] = total;
    }
}

// ---------------------------------------------------------------------------
// Main: CTA per (b,i), 256 threads, 3 CTAs/SM.
//  G1: warp w -> m-tiles {2(w&3), 2(w&3)+1} x nt in [4(w>>2), 4(w>>2)+4)
//      (B fragments loaded once per warp for 2 m-tiles -> half the B traffic)
//  G2: warp per 16 j, ushort byte-offset gather, f32x2 adds.
// smem (floats, 17472 = 69,888 B):
//   [0, 8704)      sX row-major [k*68 + d]  (A-frag banks 4g+tg: conflict-free)
//                  overlaid after G1 by tX [k*68 + e] (identical layout)
//   [8704, 17408)  sW2: f32x2 (hi,lo) [d*68 + e]
//   [17408, 17472) bias
// ---------------------------------------------------------------------------
static constexpr int SMEM_FLOATS = 17472;
static constexpr int SMEM_BYTES  = SMEM_FLOATS * 4;   // 69,888

__global__ __launch_bounds__(256, 3)
void ngnn_mma_kernel(const float* __restrict__ X,
                     const float* __restrict__ bias,
                     float* __restrict__ out) {
    extern __shared__ float sm[];
    float*  sX    = sm;                     // [k*68 + d]
    float*  tX    = sm;                     // [k*68 + e] overlay
    float2* sW2   = (float2*)(sm + 8704);   // [d*68 + e]
    float*  sbias = sm + 17408;

    const int i = blockIdx.x;
    const int b = blockIdx.y;
    const int t = threadIdx.x;
    const int warp = t >> 5;
    const int lane = t & 31;

    // ---- prologue: X rows (float4, row-major) + W fragments + bias ----
    {
        const int k = t & 127, h = t >> 7;
        const float4* xr = (const float4*)(X + (((size_t)b * Nn + i) * Nn + k) * 64 + h * 32);
        float* dst = sX + 68 * k + 32 * h;
        #pragma unroll
        for (int m = 0; m < 8; ++m) *(float4*)(dst + 4 * m) = xr[m];
        #pragma unroll
        for (int r = 0; r < 16; ++r) {
            int f = r * 256 + t;
            int d = f >> 6, e = f & 63;
            sW2[d * 68 + e] = g_wp[f];
        }
        if (t < 64) sbias[t] = bias[t];
    }
    __syncthreads();

    // ---- G1 ----
    float acc[2][4][4];
    #pragma unroll
    for (int r = 0; r < 2; ++r)
        #pragma unroll
        for (int n = 0; n < 4; ++n)
            #pragma unroll
            for (int c = 0; c < 4; ++c) acc[r][n][c] = 0.0f;

    {
        const int g  = lane >> 2;
        const int tg = lane & 3;
        const int q  = warp & 3;         // m-pair
        const int h2 = warp >> 2;        // nt-half
        #pragma unroll
        for (int s = 0; s < 8; ++s) {
            const int d0 = tg + 8 * s;   // ks0
            const int d1 = d0 + 4;       // ks1
            float hA[2][4], lA[2][4];
            #pragma unroll
            for (int r = 0; r < 2; ++r) {
                const int kb = 32 * q + 16 * r + g;
                const float x00 = sX[kb * 68 + d0];
                const float x10 = sX[(kb + 8) * 68 + d0];
                const float x01 = sX[kb * 68 + d1];
                const float x11 = sX[(kb + 8) * 68 + d1];
                hA[r][0] = __uint_as_float(tf32r(x00));
                hA[r][1] = __uint_as_float(tf32r(x10));
                hA[r][2] = __uint_as_float(tf32r(x01));
                hA[r][3] = __uint_as_float(tf32r(x11));
                lA[r][0] = __uint_as_float(tf32r(x00 - hA[r][0]));
                lA[r][1] = __uint_as_float(tf32r(x10 - hA[r][1]));
                lA[r][2] = __uint_as_float(tf32r(x01 - hA[r][2]));
                lA[r][3] = __uint_as_float(tf32r(x11 - hA[r][3]));
            }
            #pragma unroll
            for (int nl = 0; nl < 4; ++nl) {
                const int e = 8 * (4 * h2 + nl) + g;
                const float2 B0 = sW2[d0 * 68 + e];  // (ks0, col g) hi,lo
                const float2 B1 = sW2[d1 * 68 + e];  // (ks1, col g) hi,lo
                #pragma unroll
                for (int r = 0; r < 2; ++r) {
                    MMA_TF32(acc[r][nl], hA[r][0], hA[r][1], hA[r][2], hA[r][3], B0.x, B1.x);
                    MMA_TF32(acc[r][nl], lA[r][0], lA[r][1], lA[r][2], lA[r][3], B0.x, B1.x);
                    MMA_TF32(acc[r][nl], hA[r][0], hA[r][1], hA[r][2], hA[r][3], B0.y, B1.y);
                }
            }
        }
    }
    __syncthreads();   // all sX reads complete before tX overlay

    // ---- epilogue: acc -> tX rows (stride 68) ----
    {
        const int g  = lane >> 2;
        const int tg = lane & 3;
        const int q  = warp & 3;
        const int h2 = warp >> 2;
        #pragma unroll
        for (int r = 0; r < 2; ++r) {
            const int k0 = 32 * q + 16 * r + g;
            float* r0 = tX + 68 * k0;
            float* r1 = tX + 68 * (k0 + 8);
            #pragma unroll
            for (int nl = 0; nl < 4; ++nl) {
                const int e = 8 * (4 * h2 + nl) + 2 * tg;
                *(float2*)(r0 + e) = make_float2(acc[r][nl][0], acc[r][nl][1]);
                *(float2*)(r1 + e) = make_float2(acc[r][nl][2], acc[r][nl][3]);
            }
        }
    }
    __syncthreads();

    // ---- G2: warp per j; lane owns e-pair {2*lane, 2*lane+1} ----
    {
        const float2 bp = ((const float2*)sbias)[lane];
        const char* tb = (const char*)tX + 8 * lane;
        float* outp = out + (((size_t)b * Nn + i) * Nn) * 64;

        #define DO1(off) { \
            unsigned long long v = *(const unsigned long long*)(tb + (off)); \
            ADD_F32X2(acc2, acc2, v); }
        #define DO2(u) { DO1((u) & 0xFFFFu); DO1((u) >> 16); }

        #pragma unroll 2
        for (int jj = 0; jj < 16; ++jj) {
            const int j = warp * 16 + jj;
            const int cnt = __ldg(&g_cnt[b * Nn + j]);
            const unsigned short* lst = g_off + ((size_t)(b * Nn + j)) * Nn;
            unsigned long long acc2;
            {
                float ax = bp.x * (float)cnt, ay = bp.y * (float)cnt;
                asm("mov.b64 %0, {%1, %2};" : "=l"(acc2) : "f"(ax), "f"(ay));
            }
            int c = 0;
            while (c + 8 <= cnt) {
                uint4 qd = __ldg((const uint4*)(lst + c));
                DO2(qd.x); DO2(qd.y); DO2(qd.z); DO2(qd.w);
                c += 8;
            }
            const int rem = cnt - c;
            if (rem >= 4) {
                uint2 qd = __ldg((const uint2*)(lst + c));
                DO2(qd.x); DO2(qd.y);
                c += 4;
            }
            if ((rem & 2) != 0) {
                unsigned qd = __ldg((const unsigned*)(lst + c));
                DO2(qd);
                c += 2;
            }
            if ((rem & 1) != 0) {
                DO1((unsigned)__ldg(&lst[cnt - 1]));
            }
            float ox, oy;
            asm("mov.b64 {%0, %1}, %2;" : "=f"(ox), "=f"(oy) : "l"(acc2));
            *(float2*)(outp + (size_t)j * 64 + 2 * lane) = make_float2(ox, oy);
        }
        #undef DO2
        #undef DO1
    }
}

// ---------------------------------------------------------------------------
extern "C" void kernel_launch(void* const* d_in, const int* in_sizes, int n_in,
                              void* d_out, int out_size) {
    const float* X    = (const float*)d_in[0];  // [B,N,N,DIN]
    const float* A    = (const float*)d_in[1];  // [B,N,N]
    const float* W    = (const float*)d_in[2];  // [DIN,DOUT]
    const float* bias = (const float*)d_in[3];  // [DOUT]
    float* out = (float*)d_out;                 // [B,N,N,DOUT]

    build_kernel<<<Bb, 256>>>(A, W);

    cudaFuncSetAttribute(ngnn_mma_kernel,
                         cudaFuncAttributeMaxDynamicSharedMemorySize, SMEM_BYTES);
    dim3 grid(Nn, Bb);
    ngnn_mma_kernel<<<grid, 256, SMEM_BYTES>>>(X, bias, out);
}

// round 8
// speedup vs baseline: 1.4624x; 1.0731x over previous
#include <cuda_runtime.h>
#include <cuda_bf16.h>
#include <cstdint>

#define Bb 64
#define Nn 128
// DIN = DOUT = 64

// pack two f32 -> bf16x2 (lo_f in low half = even k, hi_f in high half = odd k)
__device__ __forceinline__ unsigned pack_bf16x2(float lo_f, float hi_f) {
    unsigned r;
    asm("cvt.rn.bf16x2.f32 %0, %1, %2;" : "=r"(r) : "f"(hi_f), "f"(lo_f));
    return r;
}
__device__ __forceinline__ float bf16_round(float x) {
    return __bfloat162float(__float2bfloat16(x));
}

// D += A(16x16,row,bf16) * B(16x8,col,bf16), f32 accum. Canonical layout:
//  a0=(g,{2tg,2tg+1}) a1=(g+8,{2tg,2tg+1}) a2=(g,{2tg+8,+9}) a3=(g+8,{2tg+8,+9})
//  b0=({2tg,2tg+1},g) b1=({2tg+8,+9},g);  c0/c1=(g,2tg/2tg+1) c2/c3=(g+8,...)
#define MMA_BF16(d, a0, a1, a2, a3, b0, b1) \
    asm volatile("mma.sync.aligned.m16n8k16.row.col.f32.bf16.bf16.f32 " \
        "{%0,%1,%2,%3}, {%4,%5,%6,%7}, {%8,%9}, {%0,%1,%2,%3};" \
        : "+f"((d)[0]), "+f"((d)[1]), "+f"((d)[2]), "+f"((d)[3]) \
        : "r"(a0), "r"(a1), "r"(a2), "r"(a3), "r"(b0), "r"(b1))

#define ADD_F32X2(out, a, b) asm("add.rn.f32x2 %0, %1, %2;" : "=l"(out) : "l"(a), "l"(b))

// ---------------------------------------------------------------------------
__device__ unsigned short g_off[Bb * Nn * Nn];  // per-(b,j) nz byte-offsets k*272
__device__ int            g_cnt[Bb * Nn];
__device__ unsigned       g_wph[64 * 32];       // W hi bf16x2, [e*32 + dd] (dd=d/2)
__device__ unsigned       g_wpl[64 * 32];       // W lo bf16x2

// ---------------------------------------------------------------------------
// Prep: warp-ballot column compaction of A + bf16 hi/lo split of W.
// block b: A columns of graph b; threads 0..31 also split W column e=b.
// ---------------------------------------------------------------------------
__global__ void build_kernel(const float* __restrict__ A,
                             const float* __restrict__ W) {
    const int b = blockIdx.x;
    const int t = threadIdx.x;
    const int w = t >> 5, lane = t & 31;

    if (t < 32) {                                // W split for column e = b
        const int e = b;
        float w0 = W[(2 * t) * 64 + e];
        float w1 = W[(2 * t + 1) * 64 + e];
        float h0 = bf16_round(w0), h1 = bf16_round(w1);
        g_wph[e * 32 + t] = pack_bf16x2(h0, h1);
        g_wpl[e * 32 + t] = pack_bf16x2(w0 - h0, w1 - h1);
    }

    const float* Ab = A + (size_t)b * Nn * Nn;
    #pragma unroll 1
    for (int jj = 0; jj < 16; ++jj) {
        const int j = w * 16 + jj;
        unsigned m[4];
        #pragma unroll
        for (int q = 0; q < 4; ++q) {
            float v = Ab[(size_t)(lane + 32 * q) * Nn + j];
            m[q] = __ballot_sync(0xFFFFFFFFu, v != 0.0f);
        }
        int pre[4];
        pre[0] = 0;
        pre[1] = __popc(m[0]);
        pre[2] = pre[1] + __popc(m[1]);
        pre[3] = pre[2] + __popc(m[2]);
        const int total = pre[3] + __popc(m[3]);
        unsigned short* lst = g_off + ((size_t)(b * Nn + j)) * Nn;
        const unsigned below = (1u << lane) - 1u;
        #pragma unroll
        for (int q = 0; q < 4; ++q) {
            if ((m[q] >> lane) & 1u) {
                int pos = pre[q] + __popc(m[q] & below);
                lst[pos] = (unsigned short)((lane + 32 * q) * 272);
            }
        }
        if (lane == 0) g_cnt[b * Nn + j] = total;
    }
}

// ---------------------------------------------------------------------------
// Main: CTA per (b,i), 256 threads, 4 CTAs/SM.
//  G1: bf16 3-term split MMA (m16n8k16). Warp w: m-pair {2(w&3),2(w&3)+1},
//      nt in [4(w>>2), 4(w>>2)+4). 96 MMAs/warp.
//  G2: warp per 16 j, ushort byte-offset gather, f32x2 adds (validated).
// smem (bytes, total 55,552):
//   [0, 18432)      sXh: bf16x2 hi of X, uint [k*36 + dd], dd=d/2 in [0,32)
//   [18432, 36864)  sXl: bf16x2 lo
//                   (overlay after G1: tX fp32 [k*68 + e], 34,816 B)
//   [36864, 46080)  sWh: bf16x2 hi of W, uint [e*36 + dd]
//   [46080, 55296)  sWl: bf16x2 lo
//   [55296, 55552)  bias (fp32)
// All G1 LDS banks: 4g+tg -> conflict-free (strides 36).
// ---------------------------------------------------------------------------
static constexpr int SMEM_BYTES = 55552;

__global__ __launch_bounds__(256, 4)
void ngnn_mma_kernel(const float* __restrict__ X,
                     const float* __restrict__ bias,
                     float* __restrict__ out) {
    extern __shared__ float sm[];
    unsigned* sXh   = (unsigned*)sm;                 // [k*36 + dd]
    unsigned* sXl   = sXh + 4608;                    // [k*36 + dd]
    float*    tX    = sm;                            // [k*68 + e] overlay
    unsigned* sWh   = sXh + 9216;                    // [e*36 + dd]
    unsigned* sWl   = sXh + 11520;
    float*    sbias = (float*)(sXh + 13824);

    const int i = blockIdx.x;
    const int b = blockIdx.y;
    const int t = threadIdx.x;
    const int warp = t >> 5;
    const int lane = t & 31;

    // ---- prologue: X -> bf16 hi/lo packed pairs; W fragments; bias ----
    {
        const int k = t & 127, h = t >> 7;
        const float4* xr = (const float4*)(X + (((size_t)b * Nn + i) * Nn + k) * 64 + h * 32);
        #pragma unroll
        for (int m = 0; m < 8; ++m) {
            float4 v = xr[m];
            const int dd = 16 * h + 2 * m;
            float hx = bf16_round(v.x), hy = bf16_round(v.y);
            float hz = bf16_round(v.z), hw = bf16_round(v.w);
            unsigned h01 = pack_bf16x2(hx, hy);
            unsigned h23 = pack_bf16x2(hz, hw);
            unsigned l01 = pack_bf16x2(v.x - hx, v.y - hy);
            unsigned l23 = pack_bf16x2(v.z - hz, v.w - hw);
            *(uint2*)(sXh + k * 36 + dd) = make_uint2(h01, h23);
            *(uint2*)(sXl + k * 36 + dd) = make_uint2(l01, l23);
        }
        #pragma unroll
        for (int r = 0; r < 8; ++r) {
            int f = r * 256 + t;                 // 0..2047, coalesced
            int e = f >> 5, dd = f & 31;
            sWh[e * 36 + dd] = g_wph[f];
            sWl[e * 36 + dd] = g_wpl[f];
        }
        if (t < 64) sbias[t] = bias[t];
    }
    __syncthreads();

    // ---- G1 ----
    float acc[2][4][4];
    #pragma unroll
    for (int r = 0; r < 2; ++r)
        #pragma unroll
        for (int n = 0; n < 4; ++n)
            #pragma unroll
            for (int c = 0; c < 4; ++c) acc[r][n][c] = 0.0f;

    {
        const int g  = lane >> 2;
        const int tg = lane & 3;
        const int q  = warp & 3;         // m-pair
        const int h2 = warp >> 2;        // nt-half
        #pragma unroll
        for (int s = 0; s < 4; ++s) {    // k16 chunk: k in [16s, 16s+16)
            const int dd0 = 8 * s + tg;
            const int dd1 = dd0 + 4;
            unsigned ah[2][4], al[2][4];
            #pragma unroll
            for (int r = 0; r < 2; ++r) {
                const int kb = 32 * q + 16 * r + g;
                ah[r][0] = sXh[kb * 36 + dd0];
                ah[r][1] = sXh[(kb + 8) * 36 + dd0];
                ah[r][2] = sXh[kb * 36 + dd1];
                ah[r][3] = sXh[(kb + 8) * 36 + dd1];
                al[r][0] = sXl[kb * 36 + dd0];
                al[r][1] = sXl[(kb + 8) * 36 + dd0];
                al[r][2] = sXl[kb * 36 + dd1];
                al[r][3] = sXl[(kb + 8) * 36 + dd1];
            }
            #pragma unroll
            for (int nl = 0; nl < 4; ++nl) {
                const int e = 8 * (4 * h2 + nl) + g;
                const unsigned bh0 = sWh[e * 36 + dd0];
                const unsigned bh1 = sWh[e * 36 + dd1];
                const unsigned bl0 = sWl[e * 36 + dd0];
                const unsigned bl1 = sWl[e * 36 + dd1];
                #pragma unroll
                for (int r = 0; r < 2; ++r) {
                    MMA_BF16(acc[r][nl], ah[r][0], ah[r][1], ah[r][2], ah[r][3], bh0, bh1); // hi*Whi
                    MMA_BF16(acc[r][nl], al[r][0], al[r][1], al[r][2], al[r][3], bh0, bh1); // lo*Whi
                    MMA_BF16(acc[r][nl], ah[r][0], ah[r][1], ah[r][2], ah[r][3], bl0, bl1); // hi*Wlo
                }
            }
        }
    }
    __syncthreads();   // all sX/sW reads complete before tX overlay

    // ---- epilogue: acc -> tX rows [k*68 + e] ----
    {
        const int g  = lane >> 2;
        const int tg = lane & 3;
        const int q  = warp & 3;
        const int h2 = warp >> 2;
        #pragma unroll
        for (int r = 0; r < 2; ++r) {
            const int k0 = 32 * q + 16 * r + g;
            float* r0 = tX + 68 * k0;
            float* r1 = tX + 68 * (k0 + 8);
            #pragma unroll
            for (int nl = 0; nl < 4; ++nl) {
                const int e = 8 * (4 * h2 + nl) + 2 * tg;
                *(float2*)(r0 + e) = make_float2(acc[r][nl][0], acc[r][nl][1]);
                *(float2*)(r1 + e) = make_float2(acc[r][nl][2], acc[r][nl][3]);
            }
        }
    }
    __syncthreads();

    // ---- G2: warp per j; lane owns e-pair {2*lane, 2*lane+1} ----
    {
        const float2 bp = ((const float2*)sbias)[lane];
        const char* tb = (const char*)tX + 8 * lane;
        float* outp = out + (((size_t)b * Nn + i) * Nn) * 64;

        #define DO1(off) { \
            unsigned long long v = *(const unsigned long long*)(tb + (off)); \
            ADD_F32X2(acc2, acc2, v); }
        #define DO2(u) { DO1((u) & 0xFFFFu); DO1((u) >> 16); }

        #pragma unroll 2
        for (int jj = 0; jj < 16; ++jj) {
            const int j = warp * 16 + jj;
            const int cnt = __ldg(&g_cnt[b * Nn + j]);
            const unsigned short* lst = g_off + ((size_t)(b * Nn + j)) * Nn;
            unsigned long long acc2;
            {
                float ax = bp.x * (float)cnt, ay = bp.y * (float)cnt;
                asm("mov.b64 %0, {%1, %2};" : "=l"(acc2) : "f"(ax), "f"(ay));
            }
            int c = 0;
            while (c + 8 <= cnt) {
                uint4 qd = __ldg((const uint4*)(lst + c));
                DO2(qd.x); DO2(qd.y); DO2(qd.z); DO2(qd.w);
                c += 8;
            }
            const int rem = cnt - c;
            if (rem >= 4) {
                uint2 qd = __ldg((const uint2*)(lst + c));
                DO2(qd.x); DO2(qd.y);
                c += 4;
            }
            if ((rem & 2) != 0) {
                unsigned qd = __ldg((const unsigned*)(lst + c));
                DO2(qd);
                c += 2;
            }
            if ((rem & 1) != 0) {
                DO1((unsigned)__ldg(&lst[cnt - 1]));
            }
            float ox, oy;
            asm("mov.b64 {%0, %1}, %2;" : "=f"(ox), "=f"(oy) : "l"(acc2));
            *(float2*)(outp + (size_t)j * 64 + 2 * lane) = make_float2(ox, oy);
        }
        #undef DO2
        #undef DO1
    }
}

// ---------------------------------------------------------------------------
extern "C" void kernel_launch(void* const* d_in, const int* in_sizes, int n_in,
                              void* d_out, int out_size) {
    const float* X    = (const float*)d_in[0];  // [B,N,N,DIN]
    const float* A    = (const float*)d_in[1];  // [B,N,N]
    const float* W    = (const float*)d_in[2];  // [DIN,DOUT]
    const float* bias = (const float*)d_in[3];  // [DOUT]
    float* out = (float*)d_out;                 // [B,N,N,DOUT]

    build_kernel<<<Bb, 256>>>(A, W);

    cudaFuncSetAttribute(ngnn_mma_kernel,
                         cudaFuncAttributeMaxDynamicSharedMemorySize, SMEM_BYTES);
    dim3 grid(Nn, Bb);
    ngnn_mma_kernel<<<grid, 256, SMEM_BYTES>>>(X, bias, out);
}

// round 9
// speedup vs baseline: 1.7447x; 1.1931x over previous
#include <cuda_runtime.h>
#include <cuda_fp16.h>
#include <cuda_bf16.h>
#include <cstdint>

#define Bb 64
#define Nn 128
// DIN = DOUT = 64

__device__ __forceinline__ unsigned pack_bf16x2(float lo_f, float hi_f) {
    unsigned r;
    asm("cvt.rn.bf16x2.f32 %0, %1, %2;" : "=r"(r) : "f"(hi_f), "f"(lo_f));
    return r;
}
__device__ __forceinline__ float bf16_round(float x) {
    return __bfloat162float(__float2bfloat16(x));
}
__device__ __forceinline__ unsigned pack_f16x2(float lo_f, float hi_f) {
    unsigned r;
    asm("cvt.rn.f16x2.f32 %0, %1, %2;" : "=r"(r) : "f"(hi_f), "f"(lo_f));
    return r;
}

// bf16 m16n8k16 (validated round 8)
#define MMA_BF16(d, a0, a1, a2, a3, b0, b1) \
    asm volatile("mma.sync.aligned.m16n8k16.row.col.f32.bf16.bf16.f32 " \
        "{%0,%1,%2,%3}, {%4,%5,%6,%7}, {%8,%9}, {%0,%1,%2,%3};" \
        : "+f"((d)[0]), "+f"((d)[1]), "+f"((d)[2]), "+f"((d)[3]) \
        : "r"(a0), "r"(a1), "r"(a2), "r"(a3), "r"(b0), "r"(b1))

// ---------------------------------------------------------------------------
__device__ unsigned short g_off[Bb * Nn * Nn];  // per-(b,j) nz byte-offsets k*144
__device__ int            g_cnt[Bb * Nn];
__device__ unsigned       g_wph[64 * 32];       // W hi bf16x2, [e*32 + dd]
__device__ unsigned       g_wpl[64 * 32];       // W lo bf16x2

// ---------------------------------------------------------------------------
__global__ void build_kernel(const float* __restrict__ A,
                             const float* __restrict__ W) {
    const int b = blockIdx.x;
    const int t = threadIdx.x;
    const int w = t >> 5, lane = t & 31;

    if (t < 32) {                                // W split for column e = b
        const int e = b;
        float w0 = W[(2 * t) * 64 + e];
        float w1 = W[(2 * t + 1) * 64 + e];
        float h0 = bf16_round(w0), h1 = bf16_round(w1);
        g_wph[e * 32 + t] = pack_bf16x2(h0, h1);
        g_wpl[e * 32 + t] = pack_bf16x2(w0 - h0, w1 - h1);
    }

    const float* Ab = A + (size_t)b * Nn * Nn;
    #pragma unroll 1
    for (int jj = 0; jj < 16; ++jj) {
        const int j = w * 16 + jj;
        unsigned m[4];
        #pragma unroll
        for (int q = 0; q < 4; ++q) {
            float v = Ab[(size_t)(lane + 32 * q) * Nn + j];
            m[q] = __ballot_sync(0xFFFFFFFFu, v != 0.0f);
        }
        int pre[4];
        pre[0] = 0;
        pre[1] = __popc(m[0]);
        pre[2] = pre[1] + __popc(m[1]);
        pre[3] = pre[2] + __popc(m[2]);
        const int total = pre[3] + __popc(m[3]);
        unsigned short* lst = g_off + ((size_t)(b * Nn + j)) * Nn;
        const unsigned below = (1u << lane) - 1u;
        #pragma unroll
        for (int q = 0; q < 4; ++q) {
            if ((m[q] >> lane) & 1u) {
                int pos = pre[q] + __popc(m[q] & below);
                lst[pos] = (unsigned short)((lane + 32 * q) * 144);   // fp16 row stride
            }
        }
        if (lane == 0) g_cnt[b * Nn + j] = total;
    }
}

// ---------------------------------------------------------------------------
// Main: CTA per (b,i), 256 threads, 4 CTAs/SM.
// smem (bytes, 53,504):
//   [0, 17408)      sXh: bf16x2 hi, uint [dd*136 + k]  (dd = d/2, 0..31)
//   [17408, 34816)  sXl: bf16x2 lo, uint [dd*136 + k]
//                   overlay after G1: tX16 fp16x2, uint [k*36 + ee] (ee=e/2)
//   [34816, 44032)  sWh: bf16x2 hi, uint [e*36 + dd]
//   [44032, 53248)  sWl
//   [53248, 53504)  bias fp32
// Bank audit: X STS.32 (8dd+k) CF; A-frag LDS (8tg+g) CF; W frag (4g+tg) CF;
//             tX16 STS.32 (4g+4nl+tg) CF; gather LDS.32 consecutive CF.
// ---------------------------------------------------------------------------
static constexpr int SMEM_BYTES = 53504;

__global__ __launch_bounds__(256, 4)
void ngnn_mma_kernel(const float* __restrict__ X,
                     const float* __restrict__ bias,
                     float* __restrict__ out) {
    extern __shared__ float sm[];
    unsigned* sXh   = (unsigned*)sm;                 // [dd*136 + k]
    unsigned* sXl   = sXh + 4352;
    unsigned* tX16  = (unsigned*)sm;                 // [k*36 + ee] overlay
    unsigned* sWh   = sXh + 8704;                    // [e*36 + dd]
    unsigned* sWl   = sXh + 11008;
    float*    sbias = (float*)(sXh + 13312);

    const int i = blockIdx.x;
    const int b = blockIdx.y;
    const int t = threadIdx.x;
    const int warp = t >> 5;
    const int lane = t & 31;

    // ---- prologue ----
    {
        const int k = t & 127, h = t >> 7;
        const float4* xr = (const float4*)(X + (((size_t)b * Nn + i) * Nn + k) * 64 + h * 32);
        #pragma unroll
        for (int m = 0; m < 8; ++m) {
            float4 v = xr[m];
            const int dd = 16 * h + 2 * m;
            float hx = bf16_round(v.x), hy = bf16_round(v.y);
            float hz = bf16_round(v.z), hw = bf16_round(v.w);
            sXh[dd * 136 + k]       = pack_bf16x2(hx, hy);
            sXh[(dd + 1) * 136 + k] = pack_bf16x2(hz, hw);
            sXl[dd * 136 + k]       = pack_bf16x2(v.x - hx, v.y - hy);
            sXl[(dd + 1) * 136 + k] = pack_bf16x2(v.z - hz, v.w - hw);
        }
        #pragma unroll
        for (int r = 0; r < 8; ++r) {
            int f = r * 256 + t;                 // coalesced
            int e = f >> 5, dd = f & 31;
            sWh[e * 36 + dd] = g_wph[f];
            sWl[e * 36 + dd] = g_wpl[f];
        }
        if (t < 64) sbias[t] = bias[t];
    }
    __syncthreads();

    // ---- G1: bf16 3-term split; warp: m-pair (warp&3), nt-half (warp>>2) ----
    float acc[2][4][4];
    #pragma unroll
    for (int r = 0; r < 2; ++r)
        #pragma unroll
        for (int n = 0; n < 4; ++n)
            #pragma unroll
            for (int c = 0; c < 4; ++c) acc[r][n][c] = 0.0f;

    {
        const int g  = lane >> 2;
        const int tg = lane & 3;
        const int q  = warp & 3;
        const int h2 = warp >> 2;
        #pragma unroll
        for (int s = 0; s < 4; ++s) {
            const int dd0 = 8 * s + tg;
            const int dd1 = dd0 + 4;
            unsigned ah[2][4], al[2][4];
            #pragma unroll
            for (int r = 0; r < 2; ++r) {
                const int kb = 32 * q + 16 * r + g;
                ah[r][0] = sXh[dd0 * 136 + kb];
                ah[r][1] = sXh[dd0 * 136 + kb + 8];
                ah[r][2] = sXh[dd1 * 136 + kb];
                ah[r][3] = sXh[dd1 * 136 + kb + 8];
                al[r][0] = sXl[dd0 * 136 + kb];
                al[r][1] = sXl[dd0 * 136 + kb + 8];
                al[r][2] = sXl[dd1 * 136 + kb];
                al[r][3] = sXl[dd1 * 136 + kb + 8];
            }
            #pragma unroll
            for (int nl = 0; nl < 4; ++nl) {
                const int e = 8 * (4 * h2 + nl) + g;
                const unsigned bh0 = sWh[e * 36 + dd0];
                const unsigned bh1 = sWh[e * 36 + dd1];
                const unsigned bl0 = sWl[e * 36 + dd0];
                const unsigned bl1 = sWl[e * 36 + dd1];
                #pragma unroll
                for (int r = 0; r < 2; ++r) {
                    MMA_BF16(acc[r][nl], ah[r][0], ah[r][1], ah[r][2], ah[r][3], bh0, bh1);
                    MMA_BF16(acc[r][nl], al[r][0], al[r][1], al[r][2], al[r][3], bh0, bh1);
                    MMA_BF16(acc[r][nl], ah[r][0], ah[r][1], ah[r][2], ah[r][3], bl0, bl1);
                }
            }
        }
    }
    __syncthreads();   // all sX/sW reads complete before tX16 overlay

    // ---- epilogue: acc -> tX16 fp16x2 rows [k*36 + ee] ----
    {
        const int g  = lane >> 2;
        const int tg = lane & 3;
        const int q  = warp & 3;
        const int h2 = warp >> 2;
        #pragma unroll
        for (int r = 0; r < 2; ++r) {
            const int k0 = 32 * q + 16 * r + g;
            #pragma unroll
            for (int nl = 0; nl < 4; ++nl) {
                const int ee = 4 * (4 * h2 + nl) + tg;     // e-pair index
                tX16[k0 * 36 + ee]       = pack_f16x2(acc[r][nl][0], acc[r][nl][1]);
                tX16[(k0 + 8) * 36 + ee] = pack_f16x2(acc[r][nl][2], acc[r][nl][3]);
            }
        }
    }
    __syncthreads();

    // ---- G2: warp per j; lane owns e-pair, fp16x2 gather (1 wf/element) ----
    {
        const float2 bp = ((const float2*)sbias)[lane];
        const char* tb = (const char*)tX16 + 4 * lane;
        float* outp = out + (((size_t)b * Nn + i) * Nn) * 64;

        #define DO1(off) { \
            unsigned v = *(const unsigned*)(tb + (off)); \
            float2 f = __half22float2(*(const __half2*)&v); \
            ax += f.x; ay += f.y; }
        #define DO2(u) { DO1((u) & 0xFFFFu); DO1((u) >> 16); }

        #pragma unroll 2
        for (int jj = 0; jj < 16; ++jj) {
            const int j = warp * 16 + jj;
            const int cnt = __ldg(&g_cnt[b * Nn + j]);
            const unsigned short* lst = g_off + ((size_t)(b * Nn + j)) * Nn;
            float ax = bp.x * (float)cnt;
            float ay = bp.y * (float)cnt;
            int c = 0;
            while (c + 8 <= cnt) {
                uint4 qd = __ldg((const uint4*)(lst + c));
                DO2(qd.x); DO2(qd.y); DO2(qd.z); DO2(qd.w);
                c += 8;
            }
            const int rem = cnt - c;
            if (rem >= 4) {
                uint2 qd = __ldg((const uint2*)(lst + c));
                DO2(qd.x); DO2(qd.y);
                c += 4;
            }
            if ((rem & 2) != 0) {
                unsigned qd = __ldg((const unsigned*)(lst + c));
                DO2(qd);
                c += 2;
            }
            if ((rem & 1) != 0) {
                DO1((unsigned)__ldg(&lst[cnt - 1]));
            }
            *(float2*)(outp + (size_t)j * 64 + 2 * lane) = make_float2(ax, ay);
        }
        #undef DO2
        #undef DO1
    }
}

// ---------------------------------------------------------------------------
extern "C" void kernel_launch(void* const* d_in, const int* in_sizes, int n_in,
                              void* d_out, int out_size) {
    const float* X    = (const float*)d_in[0];  // [B,N,N,DIN]
    const float* A    = (const float*)d_in[1];  // [B,N,N]
    const float* W    = (const float*)d_in[2];  // [DIN,DOUT]
    const float* bias = (const float*)d_in[3];  // [DOUT]
    float* out = (float*)d_out;                 // [B,N,N,DOUT]

    build_kernel<<<Bb, 256>>>(A, W);

    cudaFuncSetAttribute(ngnn_mma_kernel,
                         cudaFuncAttributeMaxDynamicSharedMemorySize, SMEM_BYTES);
    dim3 grid(Nn, Bb);
    ngnn_mma_kernel<<<grid, 256, SMEM_BYTES>>>(X, bias, out);
}

// round 11
// speedup vs baseline: 1.9236x; 1.1025x over previous
#include <cuda_runtime.h>
#include <cuda_fp16.h>
#include <cuda_bf16.h>
#include <cstdint>

#define Bb 64
#define Nn 128
// DIN = DOUT = 64

__device__ __forceinline__ unsigned pack_bf16x2(float lo_f, float hi_f) {
    unsigned r;
    asm("cvt.rn.bf16x2.f32 %0, %1, %2;" : "=r"(r) : "f"(hi_f), "f"(lo_f));
    return r;
}
__device__ __forceinline__ float bf16_round(float x) {
    return __bfloat162float(__float2bfloat16(x));
}
__device__ __forceinline__ unsigned pack_f16x2(float lo_f, float hi_f) {
    unsigned r;
    asm("cvt.rn.f16x2.f32 %0, %1, %2;" : "=r"(r) : "f"(hi_f), "f"(lo_f));
    return r;
}

// bf16 m16n8k16 (validated rounds 8-9)
#define MMA_BF16(d, a0, a1, a2, a3, b0, b1) \
    asm volatile("mma.sync.aligned.m16n8k16.row.col.f32.bf16.bf16.f32 " \
        "{%0,%1,%2,%3}, {%4,%5,%6,%7}, {%8,%9}, {%0,%1,%2,%3};" \
        : "+f"((d)[0]), "+f"((d)[1]), "+f"((d)[2]), "+f"((d)[3]) \
        : "r"(a0), "r"(a1), "r"(a2), "r"(a3), "r"(b0), "r"(b1))

// fp16 m16n8k16, same fragment geometry
#define MMA_F16(d, a0, a1, a2, a3, b0, b1) \
    asm volatile("mma.sync.aligned.m16n8k16.row.col.f32.f16.f16.f32 " \
        "{%0,%1,%2,%3}, {%4,%5,%6,%7}, {%8,%9}, {%0,%1,%2,%3};" \
        : "+f"((d)[0]), "+f"((d)[1]), "+f"((d)[2]), "+f"((d)[3]) \
        : "r"(a0), "r"(a1), "r"(a2), "r"(a3), "r"(b0), "r"(b1))

// ---------------------------------------------------------------------------
__device__ unsigned g_ah[Bb * Nn * 64];   // A'' fp16x2: [b][j][kk], kk = k/2 in [0,64)
__device__ unsigned g_wph[64 * 32];       // W hi bf16x2, [e*32 + dd]
__device__ unsigned g_wpl[64 * 32];       // W lo bf16x2

// ---------------------------------------------------------------------------
// Prep: transpose-pack A[b] -> fp16x2 [j][kk] via smem stage; split W.
// ---------------------------------------------------------------------------
__global__ void build_kernel(const float* __restrict__ A,
                             const float* __restrict__ W) {
    __shared__ __half sA[128 * 130];       // [j*130 + k]
    const int b = blockIdx.x;
    const int t = threadIdx.x;

    if (t < 32) {                          // W split for column e = b
        const int e = b;
        float w0 = W[(2 * t) * 64 + e];
        float w1 = W[(2 * t + 1) * 64 + e];
        float h0 = bf16_round(w0), h1 = bf16_round(w1);
        g_wph[e * 32 + t] = pack_bf16x2(h0, h1);
        g_wpl[e * 32 + t] = pack_bf16x2(w0 - h0, w1 - h1);
    }

    const float* Ab = A + (size_t)b * Nn * Nn;
    #pragma unroll 4
    for (int r = 0; r < 64; ++r) {
        int f = r * 256 + t;               // coalesced read A[k][j]
        int k = f >> 7, j = f & 127;
        sA[j * 130 + k] = __float2half(Ab[f]);
    }
    __syncthreads();

    const __half2* s2 = (const __half2*)sA;          // [j*65 + kk]
    unsigned* dst = g_ah + (size_t)b * 8192;
    #pragma unroll 4
    for (int r = 0; r < 32; ++r) {
        int u = r * 256 + t;               // coalesced write; u = j*64 + kk
        int j = u >> 6, kk = u & 63;
        __half2 p = s2[j * 65 + kk];
        dst[u] = *(const unsigned*)&p;
    }
}

// ---------------------------------------------------------------------------
// Main: CTA per (b,i), 256 threads, 4 CTAs/SM. Two chained MMAs:
//  G1 (bf16 3-term split): tX[k][e] = X[b,i]·W + bias      [validated]
//  epi: shuffle-transpose acc -> tXB fp16x2 [e][kkp] (k-pairs)
//  G2 (fp16 dense): out^T[e][j] = tX^T(e,k) x A''(k,j)
// smem (bytes, 53,504):
//  phase1: sXh [0,17408) [dd*136+k] | sXl [17408,34816) | sWh [34816,44032)
//          | sWl [44032,53248) | bias [53248,53504)
//  phase2: tXB [0,17388) uint [e*68+kkp] | sA'' [17408,52208) uint [j*68+kk]
// ---------------------------------------------------------------------------
static constexpr int SMEM_BYTES = 53504;

__global__ __launch_bounds__(256, 4)
void ngnn_mma_kernel(const float* __restrict__ X,
                     const float* __restrict__ bias,
                     float* __restrict__ out) {
    extern __shared__ float sm[];
    unsigned* sXh   = (unsigned*)sm;                 // [dd*136 + k]
    unsigned* sXl   = sXh + 4352;
    unsigned* sWh   = sXh + 8704;                    // [e*36 + dd]
    unsigned* sWl   = sXh + 11008;
    float*    sbias = (float*)(sXh + 13312);
    unsigned* tXB   = (unsigned*)sm;                 // [e*68 + kkp] overlay
    unsigned* sA2   = sXh + 4352;                    // [j*68 + kk]  overlay

    const int i = blockIdx.x;
    const int b = blockIdx.y;
    const int t = threadIdx.x;
    const int warp = t >> 5;
    const int lane = t & 31;
    const int g  = lane >> 2;
    const int tg = lane & 3;

    // ---- prologue: X -> bf16 hi/lo; W fragments; bias ----
    {
        const int k = t & 127, h = t >> 7;
        const float4* xr = (const float4*)(X + (((size_t)b * Nn + i) * Nn + k) * 64 + h * 32);
        #pragma unroll
        for (int m = 0; m < 8; ++m) {
            float4 v = xr[m];
            const int dd = 16 * h + 2 * m;
            float hx = bf16_round(v.x), hy = bf16_round(v.y);
            float hz = bf16_round(v.z), hw = bf16_round(v.w);
            sXh[dd * 136 + k]       = pack_bf16x2(hx, hy);
            sXh[(dd + 1) * 136 + k] = pack_bf16x2(hz, hw);
            sXl[dd * 136 + k]       = pack_bf16x2(v.x - hx, v.y - hy);
            sXl[(dd + 1) * 136 + k] = pack_bf16x2(v.z - hz, v.w - hw);
        }
        #pragma unroll
        for (int r = 0; r < 8; ++r) {
            int f = r * 256 + t;
            int e = f >> 5, dd = f & 31;
            sWh[e * 36 + dd] = g_wph[f];
            sWl[e * 36 + dd] = g_wpl[f];
        }
        if (t < 64) sbias[t] = bias[t];
    }
    __syncthreads();

    // ---- G1: bf16 3-term split (validated) ----
    float acc[2][4][4];
    #pragma unroll
    for (int r = 0; r < 2; ++r)
        #pragma unroll
        for (int n = 0; n < 4; ++n)
            #pragma unroll
            for (int c = 0; c < 4; ++c) acc[r][n][c] = 0.0f;

    {
        const int q  = warp & 3;
        const int h2 = warp >> 2;
        #pragma unroll
        for (int s = 0; s < 4; ++s) {
            const int dd0 = 8 * s + tg;
            const int dd1 = dd0 + 4;
            unsigned ah[2][4], al[2][4];
            #pragma unroll
            for (int r = 0; r < 2; ++r) {
                const int kb = 32 * q + 16 * r + g;
                ah[r][0] = sXh[dd0 * 136 + kb];
                ah[r][1] = sXh[dd0 * 136 + kb + 8];
                ah[r][2] = sXh[dd1 * 136 + kb];
                ah[r][3] = sXh[dd1 * 136 + kb + 8];
                al[r][0] = sXl[dd0 * 136 + kb];
                al[r][1] = sXl[dd0 * 136 + kb + 8];
                al[r][2] = sXl[dd1 * 136 + kb];
                al[r][3] = sXl[dd1 * 136 + kb + 8];
            }
            #pragma unroll
            for (int nl = 0; nl < 4; ++nl) {
                const int e = 8 * (4 * h2 + nl) + g;
                const unsigned bh0 = sWh[e * 36 + dd0];
                const unsigned bh1 = sWh[e * 36 + dd1];
                const unsigned bl0 = sWl[e * 36 + dd0];
                const unsigned bl1 = sWl[e * 36 + dd1];
                #pragma unroll
                for (int r = 0; r < 2; ++r) {
                    MMA_BF16(acc[r][nl], ah[r][0], ah[r][1], ah[r][2], ah[r][3], bh0, bh1);
                    MMA_BF16(acc[r][nl], al[r][0], al[r][1], al[r][2], al[r][3], bh0, bh1);
                    MMA_BF16(acc[r][nl], ah[r][0], ah[r][1], ah[r][2], ah[r][3], bl0, bl1);
                }
            }
        }
    }
    __syncthreads();   // all phase-1 smem reads complete

    // ---- epilogue: +bias, shuffle-transpose to tXB fp16x2 [e][kkp] ----
    {
        const int q  = warp & 3;
        const int h2 = warp >> 2;
        #pragma unroll
        for (int r = 0; r < 2; ++r) {
            const int kkp = 16 * q + 8 * r + (g >> 1);
            #pragma unroll
            for (int nl = 0; nl < 4; ++nl) {
                const float2 bv = ((const float2*)sbias)[4 * (4 * h2 + nl) + tg];
                float v0 = acc[r][nl][0] + bv.x;
                float v1 = acc[r][nl][1] + bv.y;
                float v2 = acc[r][nl][2] + bv.x;
                float v3 = acc[r][nl][3] + bv.y;
                float u0 = __shfl_xor_sync(0xFFFFFFFFu, v0, 4);
                float u1 = __shfl_xor_sync(0xFFFFFFFFu, v1, 4);
                float u2 = __shfl_xor_sync(0xFFFFFFFFu, v2, 4);
                float u3 = __shfl_xor_sync(0xFFFFFFFFu, v3, 4);
                if ((g & 1) == 0) {        // even g: rows k0 (even), partner k0+1
                    const int e0 = 8 * (4 * h2 + nl) + 2 * tg;
                    tXB[e0 * 68 + kkp]           = pack_f16x2(v0, u0);
                    tXB[(e0 + 1) * 68 + kkp]     = pack_f16x2(v1, u1);
                    tXB[e0 * 68 + kkp + 4]       = pack_f16x2(v2, u2);
                    tXB[(e0 + 1) * 68 + kkp + 4] = pack_f16x2(v3, u3);
                }
            }
        }
    }

    // ---- load A''[b] into sA'' [j*68 + kk] ----
    {
        const uint4* ga = (const uint4*)(g_ah + (size_t)b * 8192);
        #pragma unroll
        for (int r = 0; r < 8; ++r) {
            int f4 = r * 256 + t;          // uint4 index, coalesced
            int u0 = f4 * 4;
            int j = u0 >> 6, kk = u0 & 63;
            *(uint4*)(sA2 + j * 68 + kk) = ga[f4];
        }
    }
    __syncthreads();

    // ---- G2: fp16 dense MMA, D'[e][j] = tX^T x A'' ----
    float acc2[2][4][4];
    #pragma unroll
    for (int r = 0; r < 2; ++r)
        #pragma unroll
        for (int n = 0; n < 4; ++n)
            #pragma unroll
            for (int c = 0; c < 4; ++c) acc2[r][n][c] = 0.0f;

    {
        const int mtb = (warp & 1) * 2;    // m-tile base (e)
        const int ntb = (warp >> 1) * 4;   // n-tile base (j)
        #pragma unroll
        for (int s = 0; s < 8; ++s) {
            const int kk0 = 8 * s + tg;
            const int kk1 = kk0 + 4;
            unsigned a[2][4];
            #pragma unroll
            for (int r = 0; r < 2; ++r) {
                const int eb = 16 * (mtb + r) + g;
                a[r][0] = tXB[eb * 68 + kk0];
                a[r][1] = tXB[(eb + 8) * 68 + kk0];
                a[r][2] = tXB[eb * 68 + kk1];
                a[r][3] = tXB[(eb + 8) * 68 + kk1];
            }
            #pragma unroll
            for (int nl = 0; nl < 4; ++nl) {
                const int jc = 8 * (ntb + nl) + g;
                const unsigned b0 = sA2[jc * 68 + kk0];
                const unsigned b1 = sA2[jc * 68 + kk1];
                #pragma unroll
                for (int r = 0; r < 2; ++r) {
                    MMA_F16(acc2[r][nl], a[r][0], a[r][1], a[r][2], a[r][3], b0, b1);
                }
            }
        }
    }

    // ---- write out: D'[e][j] -> out[b,i,j,e] ----
    {
        float* outp = out + (((size_t)b * Nn + i) * Nn) * 64;
        const int mtb = (warp & 1) * 2;
        const int ntb = (warp >> 1) * 4;
        #pragma unroll
        for (int r = 0; r < 2; ++r) {
            const int e0 = 16 * (mtb + r) + g;
            #pragma unroll
            for (int nl = 0; nl < 4; ++nl) {
                const int j0 = 8 * (ntb + nl) + 2 * tg;
                outp[(size_t)j0 * 64 + e0]           = acc2[r][nl][0];
                outp[(size_t)(j0 + 1) * 64 + e0]     = acc2[r][nl][1];
                outp[(size_t)j0 * 64 + e0 + 8]       = acc2[r][nl][2];
                outp[(size_t)(j0 + 1) * 64 + e0 + 8] = acc2[r][nl][3];
            }
        }
    }
}

// ---------------------------------------------------------------------------
extern "C" void kernel_launch(void* const* d_in, const int* in_sizes, int n_in,
                              void* d_out, int out_size) {
    const float* X    = (const float*)d_in[0];  // [B,N,N,DIN]
    const float* A    = (const float*)d_in[1];  // [B,N,N]
    const float* W    = (const float*)d_in[2];  // [DIN,DOUT]
    const float* bias = (const float*)d_in[3];  // [DOUT]
    float* out = (float*)d_out;                 // [B,N,N,DOUT]

    build_kernel<<<Bb, 256>>>(A, W);

    cudaFuncSetAttribute(ngnn_mma_kernel,
                         cudaFuncAttributeMaxDynamicSharedMemorySize, SMEM_BYTES);
    dim3 grid(Nn, Bb);
    ngnn_mma_kernel<<<grid, 256, SMEM_BYTES>>>(X, bias, out);
}

// round 12
// speedup vs baseline: 2.4069x; 1.2513x over previous
#include <cuda_runtime.h>
#include <cuda_fp16.h>
#include <cuda_bf16.h>
#include <cstdint>

#define Bb 64
#define Nn 128
// DIN = DOUT = 64

__device__ __forceinline__ unsigned pack_bf16x2(float lo_f, float hi_f) {
    unsigned r;
    asm("cvt.rn.bf16x2.f32 %0, %1, %2;" : "=r"(r) : "f"(hi_f), "f"(lo_f));
    return r;
}
__device__ __forceinline__ float bf16_round(float x) {
    return __bfloat162float(__float2bfloat16(x));
}
__device__ __forceinline__ unsigned pack_f16x2(float lo_f, float hi_f) {
    unsigned r;
    asm("cvt.rn.f16x2.f32 %0, %1, %2;" : "=r"(r) : "f"(hi_f), "f"(lo_f));
    return r;
}

// bf16 m16n8k16 (validated rounds 8-11)
#define MMA_BF16(d, a0, a1, a2, a3, b0, b1) \
    asm volatile("mma.sync.aligned.m16n8k16.row.col.f32.bf16.bf16.f32 " \
        "{%0,%1,%2,%3}, {%4,%5,%6,%7}, {%8,%9}, {%0,%1,%2,%3};" \
        : "+f"((d)[0]), "+f"((d)[1]), "+f"((d)[2]), "+f"((d)[3]) \
        : "r"(a0), "r"(a1), "r"(a2), "r"(a3), "r"(b0), "r"(b1))

// fp16 m16n8k16, same fragment geometry (validated round 11)
#define MMA_F16(d, a0, a1, a2, a3, b0, b1) \
    asm volatile("mma.sync.aligned.m16n8k16.row.col.f32.f16.f16.f32 " \
        "{%0,%1,%2,%3}, {%4,%5,%6,%7}, {%8,%9}, {%0,%1,%2,%3};" \
        : "+f"((d)[0]), "+f"((d)[1]), "+f"((d)[2]), "+f"((d)[3]) \
        : "r"(a0), "r"(a1), "r"(a2), "r"(a3), "r"(b0), "r"(b1))

// ---------------------------------------------------------------------------
__device__ unsigned g_ah[Bb * Nn * 64];   // A'' fp16x2: [b][j][kk], kk = k/2
__device__ unsigned g_wph[64 * 32];       // W hi bf16x2, [e*32 + dd]
__device__ unsigned g_wpl[64 * 32];       // W lo bf16x2

// ---------------------------------------------------------------------------
// Prep: transpose-pack A[b] -> fp16x2 [j][kk] via smem stage; split W.
// ---------------------------------------------------------------------------
__global__ void build_kernel(const float* __restrict__ A,
                             const float* __restrict__ W) {
    __shared__ __half sA[128 * 130];       // [j*130 + k]
    const int b = blockIdx.x;
    const int t = threadIdx.x;

    if (t < 32) {                          // W split for column e = b
        const int e = b;
        float w0 = W[(2 * t) * 64 + e];
        float w1 = W[(2 * t + 1) * 64 + e];
        float h0 = bf16_round(w0), h1 = bf16_round(w1);
        g_wph[e * 32 + t] = pack_bf16x2(h0, h1);
        g_wpl[e * 32 + t] = pack_bf16x2(w0 - h0, w1 - h1);
    }

    const float* Ab = A + (size_t)b * Nn * Nn;
    #pragma unroll 4
    for (int r = 0; r < 64; ++r) {
        int f = r * 256 + t;               // coalesced read A[k][j]
        int k = f >> 7, j = f & 127;
        sA[j * 130 + k] = __float2half(Ab[f]);
    }
    __syncthreads();

    const __half2* s2 = (const __half2*)sA;          // [j*65 + kk]
    unsigned* dst = g_ah + (size_t)b * 8192;
    #pragma unroll 4
    for (int r = 0; r < 32; ++r) {
        int u = r * 256 + t;               // coalesced write; u = j*64 + kk
        int j = u >> 6, kk = u & 63;
        __half2 p = s2[j * 65 + kk];
        dst[u] = *(const unsigned*)&p;
    }
}

// ---------------------------------------------------------------------------
// Main: CTA per (b,i), 256 threads, 4 CTAs/SM. Two chained MMAs:
//  G1 (bf16 3-term split): tX[k][e] = X[b,i]·W + bias
//  epi: shuffle-transpose acc -> tXB fp16x2 [e][kkp] (full-warp STS)
//  G2 (fp16 dense): out^T[e][j] = tX^T(e,k) x A''(k,j)
// X smem layout: [dd*136 + (k ^ 2*((dd>>2)&7))] -- XOR swizzle makes both the
// coalesced-LDG STS and the G1 A-frag LDS conflict-free.
// ---------------------------------------------------------------------------
static constexpr int SMEM_BYTES = 53504;

__global__ __launch_bounds__(256, 4)
void ngnn_mma_kernel(const float* __restrict__ X,
                     const float* __restrict__ bias,
                     float* __restrict__ out) {
    extern __shared__ float sm[];
    unsigned* sXh   = (unsigned*)sm;                 // swizzled [dd][k]
    unsigned* sXl   = sXh + 4352;
    unsigned* sWh   = sXh + 8704;                    // [e*36 + dd]
    unsigned* sWl   = sXh + 11008;
    float*    sbias = (float*)(sXh + 13312);
    unsigned* tXB   = (unsigned*)sm;                 // [e*68 + kkp] overlay
    unsigned* sA2   = sXh + 4352;                    // [j*68 + kk]  overlay

    const int i = blockIdx.x;
    const int b = blockIdx.y;
    const int t = threadIdx.x;
    const int warp = t >> 5;
    const int lane = t & 31;
    const int g  = lane >> 2;
    const int tg = lane & 3;

    // ---- prologue: coalesced X LDG -> swizzled bf16 hi/lo STS; W; bias ----
    {
        const float4* xbase = (const float4*)(X + (((size_t)b * Nn + i) * Nn) * 64);
        #pragma unroll
        for (int r = 0; r < 8; ++r) {
            const int f4 = r * 256 + t;          // consecutive 16B -> coalesced
            float4 v = xbase[f4];
            const int k = f4 >> 4;               // row
            const int o = f4 & 15;               // d-chunk (4 floats)
            const unsigned xz = 2u * (unsigned)((o >> 1) & 7);
            const int kx = k ^ (int)xz;
            const int dd0 = 2 * o, dd1 = 2 * o + 1;
            float hx = bf16_round(v.x), hy = bf16_round(v.y);
            float hz = bf16_round(v.z), hw = bf16_round(v.w);
            sXh[dd0 * 136 + kx] = pack_bf16x2(hx, hy);
            sXh[dd1 * 136 + kx] = pack_bf16x2(hz, hw);
            sXl[dd0 * 136 + kx] = pack_bf16x2(v.x - hx, v.y - hy);
            sXl[dd1 * 136 + kx] = pack_bf16x2(v.z - hz, v.w - hw);
        }
        #pragma unroll
        for (int r = 0; r < 8; ++r) {
            int f = r * 256 + t;
            int e = f >> 5, dd = f & 31;
            sWh[e * 36 + dd] = g_wph[f];
            sWl[e * 36 + dd] = g_wpl[f];
        }
        if (t < 64) sbias[t] = bias[t];
    }
    __syncthreads();

    // ---- G1: bf16 3-term split ----
    float acc[2][4][4];
    #pragma unroll
    for (int r = 0; r < 2; ++r)
        #pragma unroll
        for (int n = 0; n < 4; ++n)
            #pragma unroll
            for (int c = 0; c < 4; ++c) acc[r][n][c] = 0.0f;

    {
        const int q  = warp & 3;
        const int h2 = warp >> 2;
        #pragma unroll
        for (int s = 0; s < 4; ++s) {
            const int dd0 = 8 * s + tg;
            const int dd1 = dd0 + 4;
            const int x0 = 2 * ((dd0 >> 2) & 7);   // = (4s) & 14   (tg<4)
            const int x1 = 2 * ((dd1 >> 2) & 7);   // = (4s+2) & 14
            unsigned ah[2][4], al[2][4];
            #pragma unroll
            for (int r = 0; r < 2; ++r) {
                const int kb = 32 * q + 16 * r + g;
                ah[r][0] = sXh[dd0 * 136 + (kb ^ x0)];
                ah[r][1] = sXh[dd0 * 136 + ((kb + 8) ^ x0)];
                ah[r][2] = sXh[dd1 * 136 + (kb ^ x1)];
                ah[r][3] = sXh[dd1 * 136 + ((kb + 8) ^ x1)];
                al[r][0] = sXl[dd0 * 136 + (kb ^ x0)];
                al[r][1] = sXl[dd0 * 136 + ((kb + 8) ^ x0)];
                al[r][2] = sXl[dd1 * 136 + (kb ^ x1)];
                al[r][3] = sXl[dd1 * 136 + ((kb + 8) ^ x1)];
            }
            #pragma unroll
            for (int nl = 0; nl < 4; ++nl) {
                const int e = 8 * (4 * h2 + nl) + g;
                const unsigned bh0 = sWh[e * 36 + dd0];
                const unsigned bh1 = sWh[e * 36 + dd1];
                const unsigned bl0 = sWl[e * 36 + dd0];
                const unsigned bl1 = sWl[e * 36 + dd1];
                #pragma unroll
                for (int r = 0; r < 2; ++r) {
                    MMA_BF16(acc[r][nl], ah[r][0], ah[r][1], ah[r][2], ah[r][3], bh0, bh1);
                    MMA_BF16(acc[r][nl], al[r][0], al[r][1], al[r][2], al[r][3], bh0, bh1);
                    MMA_BF16(acc[r][nl], ah[r][0], ah[r][1], ah[r][2], ah[r][3], bl0, bl1);
                }
            }
        }
    }
    __syncthreads();   // all phase-1 smem reads complete

    // ---- epilogue: +bias, shfl-transpose -> tXB; FULL-warp STS ----
    // even-g lanes write column e0 (pack(own, partner)); odd-g write e0+1
    // (pack(partner, own)). Banks 8tg + 4(g&1) + (g>>1): conflict-free.
    {
        const int q  = warp & 3;
        const int h2 = warp >> 2;
        const int gb = g & 1;
        #pragma unroll
        for (int r = 0; r < 2; ++r) {
            const int kkp = 16 * q + 8 * r + (g >> 1);
            #pragma unroll
            for (int nl = 0; nl < 4; ++nl) {
                const float2 bv = ((const float2*)sbias)[4 * (4 * h2 + nl) + tg];
                float c0 = acc[r][nl][0] + bv.x;
                float c1 = acc[r][nl][1] + bv.y;
                float c2 = acc[r][nl][2] + bv.x;
                float c3 = acc[r][nl][3] + bv.y;
                float u0 = __shfl_xor_sync(0xFFFFFFFFu, c0, 4);
                float u1 = __shfl_xor_sync(0xFFFFFFFFu, c1, 4);
                float u2 = __shfl_xor_sync(0xFFFFFFFFu, c2, 4);
                float u3 = __shfl_xor_sync(0xFFFFFFFFu, c3, 4);
                const int e0 = 8 * (4 * h2 + nl) + 2 * tg + gb;
                unsigned w0 = gb ? pack_f16x2(u1, c1) : pack_f16x2(c0, u0);
                unsigned w1 = gb ? pack_f16x2(u3, c3) : pack_f16x2(c2, u2);
                tXB[e0 * 68 + kkp]     = w0;
                tXB[e0 * 68 + kkp + 4] = w1;
            }
        }
    }

    // ---- load A''[b] into sA'' [j*68 + kk] ----
    {
        const uint4* ga = (const uint4*)(g_ah + (size_t)b * 8192);
        #pragma unroll
        for (int r = 0; r < 8; ++r) {
            int f4 = r * 256 + t;          // uint4 index, coalesced
            int u0 = f4 * 4;
            int j = u0 >> 6, kk = u0 & 63;
            *(uint4*)(sA2 + j * 68 + kk) = ga[f4];
        }
    }
    __syncthreads();

    // ---- G2: fp16 dense MMA, D'[e][j] = tX^T x A'' ----
    float acc2[2][4][4];
    #pragma unroll
    for (int r = 0; r < 2; ++r)
        #pragma unroll
        for (int n = 0; n < 4; ++n)
            #pragma unroll
            for (int c = 0; c < 4; ++c) acc2[r][n][c] = 0.0f;

    {
        const int mtb = (warp & 1) * 2;    // m-tile base (e)
        const int ntb = (warp >> 1) * 4;   // n-tile base (j)
        #pragma unroll
        for (int s = 0; s < 8; ++s) {
            const int kk0 = 8 * s + tg;
            const int kk1 = kk0 + 4;
            unsigned a[2][4];
            #pragma unroll
            for (int r = 0; r < 2; ++r) {
                const int eb = 16 * (mtb + r) + g;
                a[r][0] = tXB[eb * 68 + kk0];
                a[r][1] = tXB[(eb + 8) * 68 + kk0];
                a[r][2] = tXB[eb * 68 + kk1];
                a[r][3] = tXB[(eb + 8) * 68 + kk1];
            }
            #pragma unroll
            for (int nl = 0; nl < 4; ++nl) {
                const int jc = 8 * (ntb + nl) + g;
                const unsigned b0 = sA2[jc * 68 + kk0];
                const unsigned b1 = sA2[jc * 68 + kk1];
                #pragma unroll
                for (int r = 0; r < 2; ++r) {
                    MMA_F16(acc2[r][nl], a[r][0], a[r][1], a[r][2], a[r][3], b0, b1);
                }
            }
        }
    }

    // ---- write out: D'[e][j] -> out[b,i,j,e] ----
    {
        float* outp = out + (((size_t)b * Nn + i) * Nn) * 64;
        const int mtb = (warp & 1) * 2;
        const int ntb = (warp >> 1) * 4;
        #pragma unroll
        for (int r = 0; r < 2; ++r) {
            const int e0 = 16 * (mtb + r) + g;
            #pragma unroll
            for (int nl = 0; nl < 4; ++nl) {
                const int j0 = 8 * (ntb + nl) + 2 * tg;
                outp[(size_t)j0 * 64 + e0]           = acc2[r][nl][0];
                outp[(size_t)(j0 + 1) * 64 + e0]     = acc2[r][nl][1];
                outp[(size_t)j0 * 64 + e0 + 8]       = acc2[r][nl][2];
                outp[(size_t)(j0 + 1) * 64 + e0 + 8] = acc2[r][nl][3];
            }
        }
    }
}

// ---------------------------------------------------------------------------
extern "C" void kernel_launch(void* const* d_in, const int* in_sizes, int n_in,
                              void* d_out, int out_size) {
    const float* X    = (const float*)d_in[0];  // [B,N,N,DIN]
    const float* A    = (const float*)d_in[1];  // [B,N,N]
    const float* W    = (const float*)d_in[2];  // [DIN,DOUT]
    const float* bias = (const float*)d_in[3];  // [DOUT]
    float* out = (float*)d_out;                 // [B,N,N,DOUT]

    build_kernel<<<Bb, 256>>>(A, W);

    cudaFuncSetAttribute(ngnn_mma_kernel,
                         cudaFuncAttributeMaxDynamicSharedMemorySize, SMEM_BYTES);
    dim3 grid(Nn, Bb);
    ngnn_mma_kernel<<<grid, 256, SMEM_BYTES>>>(X, bias, out);
}

// round 13
// speedup vs baseline: 2.7282x; 1.1335x over previous
#include <cuda_runtime.h>
#include <cuda_fp16.h>
#include <cstdint>

#define Bb 64
#define Nn 128
// DIN = DOUT = 64

__device__ __forceinline__ unsigned pack_f16x2(float lo_f, float hi_f) {
    unsigned r;
    asm("cvt.rn.f16x2.f32 %0, %1, %2;" : "=r"(r) : "f"(hi_f), "f"(lo_f));
    return r;
}

// fp16 m16n8k16 (fragment geometry validated rounds 8-12)
#define MMA_F16(d, a0, a1, a2, a3, b0, b1) \
    asm volatile("mma.sync.aligned.m16n8k16.row.col.f32.f16.f16.f32 " \
        "{%0,%1,%2,%3}, {%4,%5,%6,%7}, {%8,%9}, {%0,%1,%2,%3};" \
        : "+f"((d)[0]), "+f"((d)[1]), "+f"((d)[2]), "+f"((d)[3]) \
        : "r"(a0), "r"(a1), "r"(a2), "r"(a3), "r"(b0), "r"(b1))

// ---------------------------------------------------------------------------
__device__ unsigned g_ah[Bb * Nn * 64];   // A'' fp16x2: [b][j][kk], kk = k/2
__device__ unsigned g_wp[64 * 32];        // W fp16x2: [e*32 + dd], dd = d/2

// ---------------------------------------------------------------------------
// Prep: transpose-pack A[b] -> fp16x2 [j][kk] via smem stage; pack W fp16.
// ---------------------------------------------------------------------------
__global__ void build_kernel(const float* __restrict__ A,
                             const float* __restrict__ W) {
    __shared__ __half sA[128 * 130];       // [j*130 + k]
    const int b = blockIdx.x;
    const int t = threadIdx.x;

    if (t < 32) {                          // W pack for column e = b
        const int e = b;
        float w0 = W[(2 * t) * 64 + e];
        float w1 = W[(2 * t + 1) * 64 + e];
        g_wp[e * 32 + t] = pack_f16x2(w0, w1);
    }

    const float* Ab = A + (size_t)b * Nn * Nn;
    #pragma unroll 4
    for (int r = 0; r < 64; ++r) {
        int f = r * 256 + t;               // coalesced read A[k][j]
        int k = f >> 7, j = f & 127;
        sA[j * 130 + k] = __float2half(Ab[f]);
    }
    __syncthreads();

    const __half2* s2 = (const __half2*)sA;          // [j*65 + kk]
    unsigned* dst = g_ah + (size_t)b * 8192;
    #pragma unroll 4
    for (int r = 0; r < 32; ++r) {
        int u = r * 256 + t;               // coalesced write; u = j*64 + kk
        int j = u >> 6, kk = u & 63;
        __half2 p = s2[j * 65 + kk];
        dst[u] = *(const unsigned*)&p;
    }
}

// ---------------------------------------------------------------------------
// Main: CTA per (b,i), 256 threads, 4 CTAs/SM. Two chained fp16 MMAs:
//  G1: tX[k][e] = X[b,i]·W   (single-pass fp16, f32 accum)
//  epi: +bias, shfl-transpose -> tXB fp16x2 [e][kkp]
//  G2: out^T[e][j] = tX^T(e,k) x A''(k,j)
// smem (uints, total 13120 = 52,480 B):
//  phase1: sX [0,4352) fp16x2, swizzled [dd*136 + (k ^ 2*((dd>>2)&7))]
//          sW [4352,6656) fp16x2 [e*36 + dd]
//  phase2: tXB [0,4352) [e*68+kkp] | sA'' [4352,13052) [j*68+kk]
//  sbias [13056,13120) (floats; outside both overlays)
// ---------------------------------------------------------------------------
static constexpr int SMEM_BYTES = 52480;

__global__ __launch_bounds__(256, 4)
void ngnn_mma_kernel(const float* __restrict__ X,
                     const float* __restrict__ bias,
                     float* __restrict__ out) {
    extern __shared__ float sm[];
    unsigned* sX    = (unsigned*)sm;                 // swizzled [dd][k]
    unsigned* sW    = sX + 4352;                     // [e*36 + dd]
    unsigned* tXB   = (unsigned*)sm;                 // [e*68 + kkp] overlay
    unsigned* sA2   = sX + 4352;                     // [j*68 + kk]  overlay
    float*    sbias = (float*)(sX + 13056);

    const int i = blockIdx.x;
    const int b = blockIdx.y;
    const int t = threadIdx.x;
    const int warp = t >> 5;
    const int lane = t & 31;
    const int g  = lane >> 2;
    const int tg = lane & 3;

    // ---- prologue: coalesced X LDG -> swizzled fp16x2 STS; W; bias ----
    {
        const float4* xbase = (const float4*)(X + (((size_t)b * Nn + i) * Nn) * 64);
        #pragma unroll
        for (int r = 0; r < 8; ++r) {
            const int f4 = r * 256 + t;          // consecutive 16B -> coalesced
            float4 v = xbase[f4];
            const int k = f4 >> 4;               // row
            const int o = f4 & 15;               // d-chunk (4 floats)
            const int kx = k ^ (2 * ((o >> 1) & 7));
            sX[(2 * o) * 136 + kx]     = pack_f16x2(v.x, v.y);
            sX[(2 * o + 1) * 136 + kx] = pack_f16x2(v.z, v.w);
        }
        #pragma unroll
        for (int r = 0; r < 8; ++r) {
            int f = r * 256 + t;
            int e = f >> 5, dd = f & 31;
            sW[e * 36 + dd] = g_wp[f];
        }
        if (t < 64) sbias[t] = bias[t];
    }
    __syncthreads();

    // ---- G1: single-pass fp16 MMA ----
    float acc[2][4][4];
    #pragma unroll
    for (int r = 0; r < 2; ++r)
        #pragma unroll
        for (int n = 0; n < 4; ++n)
            #pragma unroll
            for (int c = 0; c < 4; ++c) acc[r][n][c] = 0.0f;

    {
        const int q  = warp & 3;
        const int h2 = warp >> 2;
        #pragma unroll
        for (int s = 0; s < 4; ++s) {
            const int dd0 = 8 * s + tg;
            const int dd1 = dd0 + 4;
            const int x0 = 2 * ((dd0 >> 2) & 7);
            const int x1 = 2 * ((dd1 >> 2) & 7);
            unsigned ah[2][4];
            #pragma unroll
            for (int r = 0; r < 2; ++r) {
                const int kb = 32 * q + 16 * r + g;
                ah[r][0] = sX[dd0 * 136 + (kb ^ x0)];
                ah[r][1] = sX[dd0 * 136 + ((kb + 8) ^ x0)];
                ah[r][2] = sX[dd1 * 136 + (kb ^ x1)];
                ah[r][3] = sX[dd1 * 136 + ((kb + 8) ^ x1)];
            }
            #pragma unroll
            for (int nl = 0; nl < 4; ++nl) {
                const int e = 8 * (4 * h2 + nl) + g;
                const unsigned b0 = sW[e * 36 + dd0];
                const unsigned b1 = sW[e * 36 + dd1];
                #pragma unroll
                for (int r = 0; r < 2; ++r) {
                    MMA_F16(acc[r][nl], ah[r][0], ah[r][1], ah[r][2], ah[r][3], b0, b1);
                }
            }
        }
    }
    __syncthreads();   // all phase-1 smem reads complete

    // ---- epilogue: +bias, shfl-transpose -> tXB; full-warp STS ----
    {
        const int q  = warp & 3;
        const int h2 = warp >> 2;
        const int gb = g & 1;
        #pragma unroll
        for (int r = 0; r < 2; ++r) {
            const int kkp = 16 * q + 8 * r + (g >> 1);
            #pragma unroll
            for (int nl = 0; nl < 4; ++nl) {
                const float2 bv = ((const float2*)sbias)[4 * (4 * h2 + nl) + tg];
                float c0 = acc[r][nl][0] + bv.x;
                float c1 = acc[r][nl][1] + bv.y;
                float c2 = acc[r][nl][2] + bv.x;
                float c3 = acc[r][nl][3] + bv.y;
                float u0 = __shfl_xor_sync(0xFFFFFFFFu, c0, 4);
                float u1 = __shfl_xor_sync(0xFFFFFFFFu, c1, 4);
                float u2 = __shfl_xor_sync(0xFFFFFFFFu, c2, 4);
                float u3 = __shfl_xor_sync(0xFFFFFFFFu, c3, 4);
                const int e0 = 8 * (4 * h2 + nl) + 2 * tg + gb;
                unsigned w0 = gb ? pack_f16x2(u1, c1) : pack_f16x2(c0, u0);
                unsigned w1 = gb ? pack_f16x2(u3, c3) : pack_f16x2(c2, u2);
                tXB[e0 * 68 + kkp]     = w0;
                tXB[e0 * 68 + kkp + 4] = w1;
            }
        }
    }

    // ---- load A''[b] into sA'' [j*68 + kk] ----
    {
        const uint4* ga = (const uint4*)(g_ah + (size_t)b * 8192);
        #pragma unroll
        for (int r = 0; r < 8; ++r) {
            int f4 = r * 256 + t;          // uint4 index, coalesced
            int u0 = f4 * 4;
            int j = u0 >> 6, kk = u0 & 63;
            *(uint4*)(sA2 + j * 68 + kk) = ga[f4];
        }
    }
    __syncthreads();

    // ---- G2: fp16 dense MMA, D'[e][j] = tX^T x A'' ----
    float acc2[2][4][4];
    #pragma unroll
    for (int r = 0; r < 2; ++r)
        #pragma unroll
        for (int n = 0; n < 4; ++n)
            #pragma unroll
            for (int c = 0; c < 4; ++c) acc2[r][n][c] = 0.0f;

    {
        const int mtb = (warp & 1) * 2;    // m-tile base (e)
        const int ntb = (warp >> 1) * 4;   // n-tile base (j)
        #pragma unroll
        for (int s = 0; s < 8; ++s) {
            const int kk0 = 8 * s + tg;
            const int kk1 = kk0 + 4;
            unsigned a[2][4];
            #pragma unroll
            for (int r = 0; r < 2; ++r) {
                const int eb = 16 * (mtb + r) + g;
                a[r][0] = tXB[eb * 68 + kk0];
                a[r][1] = tXB[(eb + 8) * 68 + kk0];
                a[r][2] = tXB[eb * 68 + kk1];
                a[r][3] = tXB[(eb + 8) * 68 + kk1];
            }
            #pragma unroll
            for (int nl = 0; nl < 4; ++nl) {
                const int jc = 8 * (ntb + nl) + g;
                const unsigned b0 = sA2[jc * 68 + kk0];
                const unsigned b1 = sA2[jc * 68 + kk1];
                #pragma unroll
                for (int r = 0; r < 2; ++r) {
                    MMA_F16(acc2[r][nl], a[r][0], a[r][1], a[r][2], a[r][3], b0, b1);
                }
            }
        }
    }

    // ---- write out: D'[e][j] -> out[b,i,j,e] ----
    {
        float* outp = out + (((size_t)b * Nn + i) * Nn) * 64;
        const int mtb = (warp & 1) * 2;
        const int ntb = (warp >> 1) * 4;
        #pragma unroll
        for (int r = 0; r < 2; ++r) {
            const int e0 = 16 * (mtb + r) + g;
            #pragma unroll
            for (int nl = 0; nl < 4; ++nl) {
                const int j0 = 8 * (ntb + nl) + 2 * tg;
                outp[(size_t)j0 * 64 + e0]           = acc2[r][nl][0];
                outp[(size_t)(j0 + 1) * 64 + e0]     = acc2[r][nl][1];
                outp[(size_t)j0 * 64 + e0 + 8]       = acc2[r][nl][2];
                outp[(size_t)(j0 + 1) * 64 + e0 + 8] = acc2[r][nl][3];
            }
        }
    }
}

// ---------------------------------------------------------------------------
extern "C" void kernel_launch(void* const* d_in, const int* in_sizes, int n_in,
                              void* d_out, int out_size) {
    const float* X    = (const float*)d_in[0];  // [B,N,N,DIN]
    const float* A    = (const float*)d_in[1];  // [B,N,N]
    const float* W    = (const float*)d_in[2];  // [DIN,DOUT]
    const float* bias = (const float*)d_in[3];  // [DOUT]
    float* out = (float*)d_out;                 // [B,N,N,DOUT]

    build_kernel<<<Bb, 256>>>(A, W);

    cudaFuncSetAttribute(ngnn_mma_kernel,
                         cudaFuncAttributeMaxDynamicSharedMemorySize, SMEM_BYTES);
    dim3 grid(Nn, Bb);
    ngnn_mma_kernel<<<grid, 256, SMEM_BYTES>>>(X, bias, out);
}

// round 14
// speedup vs baseline: 2.8192x; 1.0333x over previous
#include <cuda_runtime.h>
#include <cuda_fp16.h>
#include <cstdint>

#define Bb 64
#define Nn 128
// DIN = DOUT = 64

__device__ __forceinline__ unsigned pack_f16x2(float lo_f, float hi_f) {
    unsigned r;
    asm("cvt.rn.f16x2.f32 %0, %1, %2;" : "=r"(r) : "f"(hi_f), "f"(lo_f));
    return r;
}
__device__ __forceinline__ uint32_t smem_u32(const void* p) {
    uint32_t a;
    asm("{ .reg .u64 t; cvta.to.shared.u64 t, %1; cvt.u32.u64 %0, t; }" : "=r"(a) : "l"(p));
    return a;
}
#define CP_ASYNC16(dst_u32, src_ptr) \
    asm volatile("cp.async.cg.shared.global [%0], [%1], 16;" :: "r"(dst_u32), "l"(src_ptr) : "memory")
#define CP_COMMIT() asm volatile("cp.async.commit_group;" ::: "memory")
#define CP_WAIT0()  asm volatile("cp.async.wait_group 0;" ::: "memory")

// fp16 m16n8k16 (fragment geometry validated rounds 8-13)
#define MMA_F16(d, a0, a1, a2, a3, b0, b1) \
    asm volatile("mma.sync.aligned.m16n8k16.row.col.f32.f16.f16.f32 " \
        "{%0,%1,%2,%3}, {%4,%5,%6,%7}, {%8,%9}, {%0,%1,%2,%3};" \
        : "+f"((d)[0]), "+f"((d)[1]), "+f"((d)[2]), "+f"((d)[3]) \
        : "r"(a0), "r"(a1), "r"(a2), "r"(a3), "r"(b0), "r"(b1))

// ---------------------------------------------------------------------------
__device__ unsigned g_ah[Bb * Nn * 64];   // A'' fp16x2: [b][j][kk], kk = k/2
__device__ unsigned g_wp[64 * 32];        // W fp16x2: [e*32 + dd], dd = d/2

// ---------------------------------------------------------------------------
__global__ void build_kernel(const float* __restrict__ A,
                             const float* __restrict__ W) {
    __shared__ __half sA[128 * 130];       // [j*130 + k]
    const int b = blockIdx.x;
    const int t = threadIdx.x;

    if (t < 32) {                          // W pack for column e = b
        const int e = b;
        float w0 = W[(2 * t) * 64 + e];
        float w1 = W[(2 * t + 1) * 64 + e];
        g_wp[e * 32 + t] = pack_f16x2(w0, w1);
    }

    const float* Ab = A + (size_t)b * Nn * Nn;
    #pragma unroll 4
    for (int r = 0; r < 64; ++r) {
        int f = r * 256 + t;               // coalesced read A[k][j]
        int k = f >> 7, j = f & 127;
        sA[j * 130 + k] = __float2half(Ab[f]);
    }
    __syncthreads();

    const __half2* s2 = (const __half2*)sA;          // [j*65 + kk]
    unsigned* dst = g_ah + (size_t)b * 8192;
    #pragma unroll 4
    for (int r = 0; r < 32; ++r) {
        int u = r * 256 + t;               // coalesced write; u = j*64 + kk
        int j = u >> 6, kk = u & 63;
        __half2 p = s2[j * 65 + kk];
        dst[u] = *(const unsigned*)&p;
    }
}

// ---------------------------------------------------------------------------
// Main: CTA per (b,i), 256 threads, 4 CTAs/SM.
//  G1: tX[k][e] = X[b,i]·W (fp16 MMA); epi: +bias, shfl -> tXB [e][kkp]
//  G2: D'[e][j] = tX^T x A''; out staged through smem for coalesced STG.
// smem (uints, 13120 = 52,480 B):
//  phase1: sX [0,4352) swizzled fp16x2 | sW [4352,6656)
//  phase2: tXB [0,4352) | sA2 [4352,13056) [j*68+kk]
//  phase3: outS fp32 [4352,13056) [j*68+e]  (reuses sA2 region)
//  sbias [13056,13120)
// A'' loaded via cp.async: rows j>=34 (disjoint from sW) before G1, rest after.
// ---------------------------------------------------------------------------
static constexpr int SMEM_BYTES = 52480;

__global__ __launch_bounds__(256, 4)
void ngnn_mma_kernel(const float* __restrict__ X,
                     const float* __restrict__ bias,
                     float* __restrict__ out) {
    extern __shared__ float sm[];
    unsigned* sX    = (unsigned*)sm;                 // swizzled [dd][k]
    unsigned* sW    = sX + 4352;                     // [e*36 + dd]
    unsigned* tXB   = (unsigned*)sm;                 // [e*68 + kkp] overlay
    unsigned* sA2   = sX + 4352;                     // [j*68 + kk]  overlay
    float*    outS  = (float*)(sX + 4352);           // [j*68 + e]   overlay
    float*    sbias = (float*)(sX + 13056);

    const int i = blockIdx.x;
    const int b = blockIdx.y;
    const int t = threadIdx.x;
    const int warp = t >> 5;
    const int lane = t & 31;
    const int g  = lane >> 2;
    const int tg = lane & 3;

    const uint32_t sa2_addr = smem_u32(sA2);
    const unsigned* gA = g_ah + (size_t)b * 8192;

    // ---- early cp.async: A'' rows j>=34 (smem [6664,13056), untouched in p1)
    {
        int f4 = 544 + t;
        while (f4 < 2048) {
            const int u0 = 4 * f4;
            const int j = u0 >> 6, kk = u0 & 63;
            CP_ASYNC16(sa2_addr + 4u * (unsigned)(j * 68 + kk), (const uint4*)(gA + u0));
            f4 += 256;
        }
        CP_COMMIT();
    }

    // ---- prologue: coalesced X LDG -> swizzled fp16x2 STS; W; bias ----
    {
        const float4* xbase = (const float4*)(X + (((size_t)b * Nn + i) * Nn) * 64);
        #pragma unroll
        for (int r = 0; r < 8; ++r) {
            const int f4 = r * 256 + t;          // consecutive 16B -> coalesced
            float4 v = xbase[f4];
            const int k = f4 >> 4;               // row
            const int o = f4 & 15;               // d-chunk (4 floats)
            const int kx = k ^ (2 * ((o >> 1) & 7));
            sX[(2 * o) * 136 + kx]     = pack_f16x2(v.x, v.y);
            sX[(2 * o + 1) * 136 + kx] = pack_f16x2(v.z, v.w);
        }
        #pragma unroll
        for (int r = 0; r < 8; ++r) {
            int f = r * 256 + t;
            int e = f >> 5, dd = f & 31;
            sW[e * 36 + dd] = g_wp[f];
        }
        if (t < 64) sbias[t] = bias[t];
    }
    __syncthreads();

    // ---- G1: single-pass fp16 MMA ----
    float acc[2][4][4];
    #pragma unroll
    for (int r = 0; r < 2; ++r)
        #pragma unroll
        for (int n = 0; n < 4; ++n)
            #pragma unroll
            for (int c = 0; c < 4; ++c) acc[r][n][c] = 0.0f;

    {
        const int q  = warp & 3;
        const int h2 = warp >> 2;
        #pragma unroll
        for (int s = 0; s < 4; ++s) {
            const int dd0 = 8 * s + tg;
            const int dd1 = dd0 + 4;
            const int x0 = 2 * ((dd0 >> 2) & 7);
            const int x1 = 2 * ((dd1 >> 2) & 7);
            unsigned ah[2][4];
            #pragma unroll
            for (int r = 0; r < 2; ++r) {
                const int kb = 32 * q + 16 * r + g;
                ah[r][0] = sX[dd0 * 136 + (kb ^ x0)];
                ah[r][1] = sX[dd0 * 136 + ((kb + 8) ^ x0)];
                ah[r][2] = sX[dd1 * 136 + (kb ^ x1)];
                ah[r][3] = sX[dd1 * 136 + ((kb + 8) ^ x1)];
            }
            #pragma unroll
            for (int nl = 0; nl < 4; ++nl) {
                const int e = 8 * (4 * h2 + nl) + g;
                const unsigned b0 = sW[e * 36 + dd0];
                const unsigned b1 = sW[e * 36 + dd1];
                #pragma unroll
                for (int r = 0; r < 2; ++r) {
                    MMA_F16(acc[r][nl], ah[r][0], ah[r][1], ah[r][2], ah[r][3], b0, b1);
                }
            }
        }
    }
    __syncthreads();   // all phase-1 smem reads complete

    // ---- late cp.async: A'' rows j<34 (overlaps sW; safe after sync) ----
    {
        int f4 = t;
        while (f4 < 544) {
            const int u0 = 4 * f4;
            const int j = u0 >> 6, kk = u0 & 63;
            CP_ASYNC16(sa2_addr + 4u * (unsigned)(j * 68 + kk), (const uint4*)(gA + u0));
            f4 += 256;
        }
        CP_COMMIT();
    }

    // ---- epilogue: +bias, shfl-transpose -> tXB; full-warp STS ----
    {
        const int q  = warp & 3;
        const int h2 = warp >> 2;
        const int gb = g & 1;
        #pragma unroll
        for (int r = 0; r < 2; ++r) {
            const int kkp = 16 * q + 8 * r + (g >> 1);
            #pragma unroll
            for (int nl = 0; nl < 4; ++nl) {
                const float2 bv = ((const float2*)sbias)[4 * (4 * h2 + nl) + tg];
                float c0 = acc[r][nl][0] + bv.x;
                float c1 = acc[r][nl][1] + bv.y;
                float c2 = acc[r][nl][2] + bv.x;
                float c3 = acc[r][nl][3] + bv.y;
                float u0 = __shfl_xor_sync(0xFFFFFFFFu, c0, 4);
                float u1 = __shfl_xor_sync(0xFFFFFFFFu, c1, 4);
                float u2 = __shfl_xor_sync(0xFFFFFFFFu, c2, 4);
                float u3 = __shfl_xor_sync(0xFFFFFFFFu, c3, 4);
                const int e0 = 8 * (4 * h2 + nl) + 2 * tg + gb;
                unsigned w0 = gb ? pack_f16x2(u1, c1) : pack_f16x2(c0, u0);
                unsigned w1 = gb ? pack_f16x2(u3, c3) : pack_f16x2(c2, u2);
                tXB[e0 * 68 + kkp]     = w0;
                tXB[e0 * 68 + kkp + 4] = w1;
            }
        }
    }

    CP_WAIT0();
    __syncthreads();

    // ---- G2: fp16 dense MMA, D'[e][j] = tX^T x A'' ----
    float acc2[2][4][4];
    #pragma unroll
    for (int r = 0; r < 2; ++r)
        #pragma unroll
        for (int n = 0; n < 4; ++n)
            #pragma unroll
            for (int c = 0; c < 4; ++c) acc2[r][n][c] = 0.0f;

    const int mtb = (warp & 1) * 2;        // m-tile base (e)
    const int ntb = (warp >> 1) * 4;       // n-tile base (j)
    {
        #pragma unroll
        for (int s = 0; s < 8; ++s) {
            const int kk0 = 8 * s + tg;
            const int kk1 = kk0 + 4;
            unsigned a[2][4];
            #pragma unroll
            for (int r = 0; r < 2; ++r) {
                const int eb = 16 * (mtb + r) + g;
                a[r][0] = tXB[eb * 68 + kk0];
                a[r][1] = tXB[(eb + 8) * 68 + kk0];
                a[r][2] = tXB[eb * 68 + kk1];
                a[r][3] = tXB[(eb + 8) * 68 + kk1];
            }
            #pragma unroll
            for (int nl = 0; nl < 4; ++nl) {
                const int jc = 8 * (ntb + nl) + g;
                const unsigned b0 = sA2[jc * 68 + kk0];
                const unsigned b1 = sA2[jc * 68 + kk1];
                #pragma unroll
                for (int r = 0; r < 2; ++r) {
                    MMA_F16(acc2[r][nl], a[r][0], a[r][1], a[r][2], a[r][3], b0, b1);
                }
            }
        }
    }
    __syncthreads();   // all sA2 reads done before outS overwrite

    // ---- stage D'[e][j] -> outS [j*68 + e] (CF: banks 8tg+g+const) ----
    {
        #pragma unroll
        for (int r = 0; r < 2; ++r) {
            const int e0 = 16 * (mtb + r) + g;
            #pragma unroll
            for (int nl = 0; nl < 4; ++nl) {
                const int j0 = 8 * (ntb + nl) + 2 * tg;
                outS[j0 * 68 + e0]           = acc2[r][nl][0];
                outS[(j0 + 1) * 68 + e0]     = acc2[r][nl][1];
                outS[j0 * 68 + e0 + 8]       = acc2[r][nl][2];
                outS[(j0 + 1) * 68 + e0 + 8] = acc2[r][nl][3];
            }
        }
    }
    __syncthreads();

    // ---- coalesced copy outS -> out[b,i,:,:] ----
    {
        float4* outp = (float4*)(out + (((size_t)b * Nn + i) * Nn) * 64);
        #pragma unroll
        for (int r = 0; r < 8; ++r) {
            const int f4 = r * 256 + t;
            const int j = f4 >> 4, c4 = f4 & 15;
            outp[f4] = *(const float4*)(outS + j * 68 + 4 * c4);
        }
    }
}

// ---------------------------------------------------------------------------
extern "C" void kernel_launch(void* const* d_in, const int* in_sizes, int n_in,
                              void* d_out, int out_size) {
    const float* X    = (const float*)d_in[0];  // [B,N,N,DIN]
    const float* A    = (const float*)d_in[1];  // [B,N,N]
    const float* W    = (const float*)d_in[2];  // [DIN,DOUT]
    const float* bias = (const float*)d_in[3];  // [DOUT]
    float* out = (float*)d_out;                 // [B,N,N,DOUT]

    build_kernel<<<Bb, 256>>>(A, W);

    cudaFuncSetAttribute(ngnn_mma_kernel,
                         cudaFuncAttributeMaxDynamicSharedMemorySize, SMEM_BYTES);
    dim3 grid(Nn, Bb);
    ngnn_mma_kernel<<<grid, 256, SMEM_BYTES>>>(X, bias, out);
}

// round 15
// speedup vs baseline: 2.9805x; 1.0572x over previous
#include <cuda_runtime.h>
#include <cuda_fp16.h>
#include <cstdint>

#define Bb 64
#define Nn 128
// DIN = DOUT = 64

__device__ __forceinline__ unsigned pack_f16x2(float lo_f, float hi_f) {
    unsigned r;
    asm("cvt.rn.f16x2.f32 %0, %1, %2;" : "=r"(r) : "f"(hi_f), "f"(lo_f));
    return r;
}

// fp16 m16n8k16 (fragment geometry validated rounds 8-14)
#define MMA_F16(d, a0, a1, a2, a3, b0, b1) \
    asm volatile("mma.sync.aligned.m16n8k16.row.col.f32.f16.f16.f32 " \
        "{%0,%1,%2,%3}, {%4,%5,%6,%7}, {%8,%9}, {%0,%1,%2,%3};" \
        : "+f"((d)[0]), "+f"((d)[1]), "+f"((d)[2]), "+f"((d)[3]) \
        : "r"(a0), "r"(a1), "r"(a2), "r"(a3), "r"(b0), "r"(b1))

// expand 2 adjacency bits (bit0 -> low fp16, bit1 -> high fp16) into fp16x2
__device__ __forceinline__ unsigned bits2_f16x2(unsigned w, int base) {
    unsigned t = (w >> base) & 3u;
    t = (t | (t << 15)) & 0x10001u;
    return t * 0x3C00u;
}

// ---------------------------------------------------------------------------
__device__ unsigned g_ab[Bb * Nn * 4];    // A bitmask: [b][j][q], bit p of word q = A[32q+p][j]
__device__ unsigned g_wp[64 * 32];        // W fp16x2: [e*32 + dd], dd = d/2

// ---------------------------------------------------------------------------
// Prep: ballot-compact A columns into bitmasks (round-6-validated indexing);
// pack W fp16.
// ---------------------------------------------------------------------------
__global__ void build_kernel(const float* __restrict__ A,
                             const float* __restrict__ W) {
    const int b = blockIdx.x;
    const int t = threadIdx.x;
    const int w = t >> 5, lane = t & 31;

    if (t < 32) {                          // W pack for column e = b
        const int e = b;
        float w0 = W[(2 * t) * 64 + e];
        float w1 = W[(2 * t + 1) * 64 + e];
        g_wp[e * 32 + t] = pack_f16x2(w0, w1);
    }

    const float* Ab = A + (size_t)b * Nn * Nn;
    #pragma unroll 1
    for (int jj = 0; jj < 16; ++jj) {
        const int j = w * 16 + jj;
        unsigned m0 = __ballot_sync(0xFFFFFFFFu, Ab[(size_t)(lane      ) * Nn + j] != 0.0f);
        unsigned m1 = __ballot_sync(0xFFFFFFFFu, Ab[(size_t)(lane +  32) * Nn + j] != 0.0f);
        unsigned m2 = __ballot_sync(0xFFFFFFFFu, Ab[(size_t)(lane +  64) * Nn + j] != 0.0f);
        unsigned m3 = __ballot_sync(0xFFFFFFFFu, Ab[(size_t)(lane +  96) * Nn + j] != 0.0f);
        if (lane == 0)
            *(uint4*)(g_ab + ((size_t)(b * Nn + j)) * 4) = make_uint4(m0, m1, m2, m3);
    }
}

// ---------------------------------------------------------------------------
// Main: CTA per (b,i), 256 threads, 4 CTAs/SM.
//  G1: tX[k][e] = X[b,i]·W (fp16 MMA); epi: +bias, shfl -> tXB [e][kkp]
//  G2: D'[e][j] = tX^T x A, with A fragments SYNTHESIZED from a bitmask.
//  out staged through smem for coalesced STG.
// smem (uints, 8768 = 35,072 B):
//  phase1: sX [0,4352) swizzled fp16x2 | sW [4352,6656) | sM [6656,7168)
//  phase2: tXB [0,4352) overlay | sM live
//  phase3: outS fp32 [0,8704) overlay (covers sX/sW/sM, all dead)
//  sbias [8704,8768)
// ---------------------------------------------------------------------------
static constexpr int SMEM_BYTES = 35072;

__global__ __launch_bounds__(256, 4)
void ngnn_mma_kernel(const float* __restrict__ X,
                     const float* __restrict__ bias,
                     float* __restrict__ out) {
    extern __shared__ float sm[];
    unsigned* sX    = (unsigned*)sm;                 // swizzled [dd][k]
    unsigned* sW    = sX + 4352;                     // [e*36 + dd]
    unsigned* sM    = sX + 6656;                     // [j*4 + q] bitmask
    unsigned* tXB   = (unsigned*)sm;                 // [e*68 + kkp] overlay
    float*    outS  = (float*)sm;                    // [j*68 + e]   overlay
    float*    sbias = (float*)(sX + 8704);

    const int i = blockIdx.x;
    const int b = blockIdx.y;
    const int t = threadIdx.x;
    const int warp = t >> 5;
    const int lane = t & 31;
    const int g  = lane >> 2;
    const int tg = lane & 3;

    // ---- prologue: coalesced X LDG -> swizzled fp16x2 STS; W; mask; bias ----
    {
        const float4* xbase = (const float4*)(X + (((size_t)b * Nn + i) * Nn) * 64);
        #pragma unroll
        for (int r = 0; r < 8; ++r) {
            const int f4 = r * 256 + t;          // consecutive 16B -> coalesced
            float4 v = xbase[f4];
            const int k = f4 >> 4;               // row
            const int o = f4 & 15;               // d-chunk (4 floats)
            const int kx = k ^ (2 * ((o >> 1) & 7));
            sX[(2 * o) * 136 + kx]     = pack_f16x2(v.x, v.y);
            sX[(2 * o + 1) * 136 + kx] = pack_f16x2(v.z, v.w);
        }
        #pragma unroll
        for (int r = 0; r < 8; ++r) {
            int f = r * 256 + t;
            int e = f >> 5, dd = f & 31;
            sW[e * 36 + dd] = g_wp[f];
        }
        #pragma unroll
        for (int r = 0; r < 2; ++r) {
            int f = r * 256 + t;                 // 512 mask words, coalesced
            sM[f] = g_ab[(size_t)b * 512 + f];
        }
        if (t < 64) sbias[t] = bias[t];
    }
    __syncthreads();

    // ---- G1: single-pass fp16 MMA ----
    float acc[2][4][4];
    #pragma unroll
    for (int r = 0; r < 2; ++r)
        #pragma unroll
        for (int n = 0; n < 4; ++n)
            #pragma unroll
            for (int c = 0; c < 4; ++c) acc[r][n][c] = 0.0f;

    {
        const int q  = warp & 3;
        const int h2 = warp >> 2;
        #pragma unroll
        for (int s = 0; s < 4; ++s) {
            const int dd0 = 8 * s + tg;
            const int dd1 = dd0 + 4;
            const int x0 = 2 * ((dd0 >> 2) & 7);
            const int x1 = 2 * ((dd1 >> 2) & 7);
            unsigned ah[2][4];
            #pragma unroll
            for (int r = 0; r < 2; ++r) {
                const int kb = 32 * q + 16 * r + g;
                ah[r][0] = sX[dd0 * 136 + (kb ^ x0)];
                ah[r][1] = sX[dd0 * 136 + ((kb + 8) ^ x0)];
                ah[r][2] = sX[dd1 * 136 + (kb ^ x1)];
                ah[r][3] = sX[dd1 * 136 + ((kb + 8) ^ x1)];
            }
            #pragma unroll
            for (int nl = 0; nl < 4; ++nl) {
                const int e = 8 * (4 * h2 + nl) + g;
                const unsigned b0 = sW[e * 36 + dd0];
                const unsigned b1 = sW[e * 36 + dd1];
                #pragma unroll
                for (int r = 0; r < 2; ++r) {
                    MMA_F16(acc[r][nl], ah[r][0], ah[r][1], ah[r][2], ah[r][3], b0, b1);
                }
            }
        }
    }
    __syncthreads();   // all sX/sW reads complete before tXB overlay

    // ---- epilogue: +bias, shfl-transpose -> tXB; full-warp STS ----
    {
        const int q  = warp & 3;
        const int h2 = warp >> 2;
        const int gb = g & 1;
        #pragma unroll
        for (int r = 0; r < 2; ++r) {
            const int kkp = 16 * q + 8 * r + (g >> 1);
            #pragma unroll
            for (int nl = 0; nl < 4; ++nl) {
                const float2 bv = ((const float2*)sbias)[4 * (4 * h2 + nl) + tg];
                float c0 = acc[r][nl][0] + bv.x;
                float c1 = acc[r][nl][1] + bv.y;
                float c2 = acc[r][nl][2] + bv.x;
                float c3 = acc[r][nl][3] + bv.y;
                float u0 = __shfl_xor_sync(0xFFFFFFFFu, c0, 4);
                float u1 = __shfl_xor_sync(0xFFFFFFFFu, c1, 4);
                float u2 = __shfl_xor_sync(0xFFFFFFFFu, c2, 4);
                float u3 = __shfl_xor_sync(0xFFFFFFFFu, c3, 4);
                const int e0 = 8 * (4 * h2 + nl) + 2 * tg + gb;
                unsigned w0 = gb ? pack_f16x2(u1, c1) : pack_f16x2(c0, u0);
                unsigned w1 = gb ? pack_f16x2(u3, c3) : pack_f16x2(c2, u2);
                tXB[e0 * 68 + kkp]     = w0;
                tXB[e0 * 68 + kkp + 4] = w1;
            }
        }
    }
    __syncthreads();

    // ---- G2: fp16 MMA, D'[e][j] = tX^T x A, B-frags from bitmask ----
    float acc2[2][4][4];
    #pragma unroll
    for (int r = 0; r < 2; ++r)
        #pragma unroll
        for (int n = 0; n < 4; ++n)
            #pragma unroll
            for (int c = 0; c < 4; ++c) acc2[r][n][c] = 0.0f;

    const int mtb = (warp & 1) * 2;        // m-tile base (e)
    const int ntb = (warp >> 1) * 4;       // n-tile base (j)
    {
        // mask words for this warp's 4 j-rows (broadcast LDS.128, CF)
        uint4 mw[4];
        #pragma unroll
        for (int nl = 0; nl < 4; ++nl) {
            const int jc = 8 * (ntb + nl) + g;
            mw[nl] = *(const uint4*)(sM + 4 * jc);
        }
        #pragma unroll
        for (int s = 0; s < 8; ++s) {
            const int kk0 = 8 * s + tg;
            const int kk1 = kk0 + 4;
            const int base = (s & 1) * 16 + 2 * tg;
            unsigned a[2][4];
            #pragma unroll
            for (int r = 0; r < 2; ++r) {
                const int eb = 16 * (mtb + r) + g;
                a[r][0] = tXB[eb * 68 + kk0];
                a[r][1] = tXB[(eb + 8) * 68 + kk0];
                a[r][2] = tXB[eb * 68 + kk1];
                a[r][3] = tXB[(eb + 8) * 68 + kk1];
            }
            #pragma unroll
            for (int nl = 0; nl < 4; ++nl) {
                const unsigned w = (s < 2) ? mw[nl].x : (s < 4) ? mw[nl].y
                                 : (s < 6) ? mw[nl].z : mw[nl].w;
                const unsigned b0 = bits2_f16x2(w, base);
                const unsigned b1 = bits2_f16x2(w, base + 8);
                #pragma unroll
                for (int r = 0; r < 2; ++r) {
                    MMA_F16(acc2[r][nl], a[r][0], a[r][1], a[r][2], a[r][3], b0, b1);
                }
            }
        }
    }
    __syncthreads();   // tXB + sM reads done before outS overwrite

    // ---- stage D'[e][j] -> outS [j*68 + e] (CF banks) ----
    {
        #pragma unroll
        for (int r = 0; r < 2; ++r) {
            const int e0 = 16 * (mtb + r) + g;
            #pragma unroll
            for (int nl = 0; nl < 4; ++nl) {
                const int j0 = 8 * (ntb + nl) + 2 * tg;
                outS[j0 * 68 + e0]           = acc2[r][nl][0];
                outS[(j0 + 1) * 68 + e0]     = acc2[r][nl][1];
                outS[j0 * 68 + e0 + 8]       = acc2[r][nl][2];
                outS[(j0 + 1) * 68 + e0 + 8] = acc2[r][nl][3];
            }
        }
    }
    __syncthreads();

    // ---- coalesced copy outS -> out[b,i,:,:] ----
    {
        float4* outp = (float4*)(out + (((size_t)b * Nn + i) * Nn) * 64);
        #pragma unroll
        for (int r = 0; r < 8; ++r) {
            const int f4 = r * 256 + t;
            const int j = f4 >> 4, c4 = f4 & 15;
            outp[f4] = *(const float4*)(outS + j * 68 + 4 * c4);
        }
    }
}

// ---------------------------------------------------------------------------
extern "C" void kernel_launch(void* const* d_in, const int* in_sizes, int n_in,
                              void* d_out, int out_size) {
    const float* X    = (const float*)d_in[0];  // [B,N,N,DIN]
    const float* A    = (const float*)d_in[1];  // [B,N,N]
    const float* W    = (const float*)d_in[2];  // [DIN,DOUT]
    const float* bias = (const float*)d_in[3];  // [DOUT]
    float* out = (float*)d_out;                 // [B,N,N,DOUT]

    build_kernel<<<Bb, 256>>>(A, W);

    cudaFuncSetAttribute(ngnn_mma_kernel,
                         cudaFuncAttributeMaxDynamicSharedMemorySize, SMEM_BYTES);
    dim3 grid(Nn, Bb);
    ngnn_mma_kernel<<<grid, 256, SMEM_BYTES>>>(X, bias, out);
}